// round 1
// baseline (speedup 1.0000x reference)
#include <cuda_runtime.h>
#include <cstdint>

#define NPTS 262144
#define KNN  16

// ---------------- device scratch (no allocations allowed) ----------------
__device__ float d_h2 [NPTS * 64];   // after mlp1+mlp2 (relu)
__device__ float d_xgm[NPTS * 64];   // neighbor max-pooled
__device__ float d_h4 [NPTS * 128];  // after mlp3+mlp4 (relu)
__device__ float d_g  [1024];        // global max pooled features
__device__ float d_f1 [512];
__device__ float d_f2 [256];

// ---------------- packed f32x2 helpers (sm_103a) ----------------
__device__ __forceinline__ unsigned long long pk2(float v) {
    unsigned long long r;
    asm("mov.b64 %0, {%1, %1};" : "=l"(r) : "f"(v));
    return r;
}
__device__ __forceinline__ void fma2(unsigned long long& d,
                                     unsigned long long a,
                                     unsigned long long b) {
    asm("fma.rn.f32x2 %0, %1, %2, %0;" : "+l"(d) : "l"(a), "l"(b));
}
__device__ __forceinline__ float2 up2(unsigned long long v) {
    float2 f;
    asm("mov.b64 {%0, %1}, %2;" : "=f"(f.x), "=f"(f.y) : "l"(v));
    return f;
}

// ---------------- zero the global-max accumulator (per launch!) ----------------
__global__ void k_zero_g() {
    d_g[blockIdx.x * 256 + threadIdx.x] = 0.0f;
}

// ---------------- mlp1 + mlp2 : x[N,3] -> h2[N,64] ----------------
// thread per point; h1 in regs; weights broadcast from smem; coalesced output via smem staging
__global__ void __launch_bounds__(256) k_mlp12(const float* __restrict__ x,
                                               const float* __restrict__ w1,
                                               const float* __restrict__ w2) {
    extern __shared__ float sm[];
    float* s_w1  = sm;                 // 192 floats
    float* s_w2  = sm + 192;           // 4096 floats (16B aligned: 192*4=768)
    float* s_out = sm + 192 + 4096;    // 256*66 floats

    int t = threadIdx.x;
    for (int i = t; i < 192;  i += 256) s_w1[i] = w1[i];
    for (int i = t; i < 4096; i += 256) s_w2[i] = w2[i];
    __syncthreads();

    int p = blockIdx.x * 256 + t;
    float x0 = x[p * 3 + 0], x1 = x[p * 3 + 1], x2 = x[p * 3 + 2];

    float h1[64];
#pragma unroll
    for (int j = 0; j < 64; j++) {
        float a = s_w1[j * 3 + 0] * x0 + s_w1[j * 3 + 1] * x1 + s_w1[j * 3 + 2] * x2;
        h1[j] = fmaxf(a, 0.0f);
    }

    for (int j = 0; j < 64; j++) {
        const float4* wr = (const float4*)&s_w2[j * 64];   // uniform -> broadcast LDS
        float a0 = 0.f, a1 = 0.f, a2 = 0.f, a3 = 0.f;
#pragma unroll
        for (int kk = 0; kk < 16; kk++) {
            float4 wv = wr[kk];
            a0 = fmaf(wv.x, h1[4 * kk + 0], a0);
            a1 = fmaf(wv.y, h1[4 * kk + 1], a1);
            a2 = fmaf(wv.z, h1[4 * kk + 2], a2);
            a3 = fmaf(wv.w, h1[4 * kk + 3], a3);
        }
        s_out[t * 66 + j] = fmaxf((a0 + a1) + (a2 + a3), 0.0f);
    }
    __syncthreads();

    size_t p0 = (size_t)blockIdx.x * 256;
    for (int i = t; i < 256 * 64; i += 256)
        d_h2[p0 * 64 + i] = s_out[(i >> 6) * 66 + (i & 63)];
}

// ---------------- graph max pooling : fixed degree K=16 ----------------
// 64 threads per point (one per feature); 256 B coalesced gather per neighbor row
__global__ void __launch_bounds__(256) k_gmax(const int* __restrict__ indices) {
    __shared__ int s_idx[4][16];
    int t  = threadIdx.x;
    int f  = t & 63;
    int pl = t >> 6;
    int p0 = blockIdx.x * 4;
    if (t < 64) s_idx[t >> 4][t & 15] = indices[p0 * 16 + t];
    __syncthreads();

    float m = 0.0f;  // h2 >= 0 (relu), so 0 is a valid identity
#pragma unroll
    for (int j = 0; j < 16; j++)
        m = fmaxf(m, d_h2[(size_t)s_idx[pl][j] * 64 + f]);

    d_xgm[(size_t)(p0 + pl) * 64 + f] = m;
}

// ---------------- mlp3 + mlp4 : h2[N,64] -> h4[N,128] ----------------
// thread per point; h2 and h3 staged in padded smem; coalesced in/out
__global__ void __launch_bounds__(128) k_mlp34(const float* __restrict__ w3,
                                               const float* __restrict__ w4) {
    extern __shared__ float sb[];
    float* s_io = sb;                 // 128*130 floats (in phase uses stride 68)
    float* s_h3 = sb + 128 * 130;     // 128*68 floats

    int t = threadIdx.x;
    size_t p0 = (size_t)blockIdx.x * 128;

    for (int i = t; i < 128 * 64; i += 128)
        s_io[(i >> 6) * 68 + (i & 63)] = d_h2[p0 * 64 + i];
    __syncthreads();

    const float4* srow = (const float4*)&s_io[t * 68];   // 272B stride, 16B aligned
    for (int j = 0; j < 64; j++) {
        const float4* wr = (const float4*)&w3[j * 64];
        float a0 = 0.f, a1 = 0.f, a2 = 0.f, a3 = 0.f;
#pragma unroll
        for (int kk = 0; kk < 16; kk++) {
            float4 wv = __ldg(&wr[kk]);   // uniform address -> 1 sector, L1-hit
            float4 sv = srow[kk];
            a0 = fmaf(wv.x, sv.x, a0);
            a1 = fmaf(wv.y, sv.y, a1);
            a2 = fmaf(wv.z, sv.z, a2);
            a3 = fmaf(wv.w, sv.w, a3);
        }
        s_h3[t * 68 + j] = fmaxf((a0 + a1) + (a2 + a3), 0.0f);
    }
    __syncthreads();  // s_io reads done before overwrite below

    const float4* hrow = (const float4*)&s_h3[t * 68];
    for (int j = 0; j < 128; j++) {
        const float4* wr = (const float4*)&w4[j * 64];
        float a0 = 0.f, a1 = 0.f, a2 = 0.f, a3 = 0.f;
#pragma unroll
        for (int kk = 0; kk < 16; kk++) {
            float4 wv = __ldg(&wr[kk]);
            float4 hv = hrow[kk];
            a0 = fmaf(wv.x, hv.x, a0);
            a1 = fmaf(wv.y, hv.y, a1);
            a2 = fmaf(wv.z, hv.z, a2);
            a3 = fmaf(wv.w, hv.w, a3);
        }
        s_io[t * 130 + j] = fmaxf((a0 + a1) + (a2 + a3), 0.0f);
    }
    __syncthreads();

    for (int i = t; i < 128 * 128; i += 128)
        d_h4[p0 * 128 + i] = s_io[(i >> 7) * 130 + (i & 127)];
}

// ---------------- mlp5 + global max : [N,192] @ [192,1024]^T, max over N ----------------
// 64-row tile per block, loops all 16 column tiles (A loaded from DRAM once).
// 256 threads, 4x4 microtile via packed f32x2 FMAs. Max folded in epilogue.
__global__ void __launch_bounds__(256) k_mlp5max(const float* __restrict__ w5) {
    extern __shared__ float sm[];
    float* s_a = sm;                 // 64 rows * stride 196  (conflict-free row loads)
    float* s_b = sm + 64 * 196;      // 192 k * 64 cols       (k-major, 16B aligned)

    int t  = threadIdx.x;
    int tr = t >> 4;                 // 0..15 -> rows tr*4..tr*4+3
    int tc = t & 15;                 // 0..15 -> cols tc*4..tc*4+3
    size_t m0 = (size_t)blockIdx.x * 64;

    // load A tile (concat: k<64 from xgm, k>=64 from h4), once
    for (int i = t; i < 64 * 48; i += 256) {
        int row = i / 48, c4 = i % 48;
        float4 v;
        if (c4 < 16) v = *(const float4*)&d_xgm[(m0 + row) * 64  + 4 * c4];
        else         v = *(const float4*)&d_h4 [(m0 + row) * 128 + 4 * c4 - 64];
        *(float4*)&s_a[row * 196 + 4 * c4] = v;
    }

    for (int nt = 0; nt < 16; nt++) {
        __syncthreads();  // protects s_b reuse (tiles + reduction buffer) and first A use
        // load B tile: w5 rows nt*64..+63, store k-major
        for (int i = t; i < 64 * 48; i += 256) {
            int col = i / 48, c4 = i % 48;
            float4 v = *(const float4*)&w5[(size_t)(nt * 64 + col) * 192 + 4 * c4];
            s_b[(4 * c4 + 0) * 64 + col] = v.x;
            s_b[(4 * c4 + 1) * 64 + col] = v.y;
            s_b[(4 * c4 + 2) * 64 + col] = v.z;
            s_b[(4 * c4 + 3) * 64 + col] = v.w;
        }
        __syncthreads();

        unsigned long long acc[4][2];
#pragma unroll
        for (int i = 0; i < 4; i++) { acc[i][0] = 0ull; acc[i][1] = 0ull; }

#pragma unroll 2
        for (int q = 0; q < 48; q++) {
            float4 a4[4];
#pragma unroll
            for (int i = 0; i < 4; i++)
                a4[i] = *(const float4*)&s_a[(tr * 4 + i) * 196 + 4 * q];
#pragma unroll
            for (int d = 0; d < 4; d++) {
                const ulonglong2 bv =
                    *(const ulonglong2*)&s_b[(4 * q + d) * 64 + tc * 4];
#pragma unroll
                for (int i = 0; i < 4; i++) {
                    float av = (d == 0) ? a4[i].x : (d == 1) ? a4[i].y
                             : (d == 2) ? a4[i].z : a4[i].w;
                    unsigned long long pa = pk2(av);
                    fma2(acc[i][0], pa, bv.x);
                    fma2(acc[i][1], pa, bv.y);
                }
            }
        }

        // fold the 4 local rows (max is commutative with the later relu)
        float cm[4];
#pragma unroll
        for (int j2 = 0; j2 < 2; j2++) {
            float2 r0 = up2(acc[0][j2]), r1 = up2(acc[1][j2]);
            float2 r2 = up2(acc[2][j2]), r3 = up2(acc[3][j2]);
            cm[2 * j2 + 0] = fmaxf(fmaxf(r0.x, r1.x), fmaxf(r2.x, r3.x));
            cm[2 * j2 + 1] = fmaxf(fmaxf(r0.y, r1.y), fmaxf(r2.y, r3.y));
        }
        __syncthreads();  // everyone done reading s_b tile
#pragma unroll
        for (int j = 0; j < 4; j++)
            s_b[tr * 64 + tc * 4 + j] = cm[j];   // reuse s_b as 16x64 reduce buffer
        __syncthreads();
        if (t < 64) {
            float m = s_b[t];
#pragma unroll
            for (int r = 1; r < 16; r++) m = fmaxf(m, s_b[r * 64 + t]);
            m = fmaxf(m, 0.0f);  // relu; non-negative floats order as ints
            atomicMax((int*)&d_g[nt * 64 + t], __float_as_int(m));
        }
    }
}

// ---------------- head: 3 small GEMVs ----------------
__device__ __forceinline__ float blk_dot_reduce(float a) {
#pragma unroll
    for (int o = 16; o; o >>= 1) a += __shfl_xor_sync(0xffffffffu, a, o);
    __shared__ float s[4];
    int t = threadIdx.x;
    if ((t & 31) == 0) s[t >> 5] = a;
    __syncthreads();
    return s[0] + s[1] + s[2] + s[3];
}

__global__ void __launch_bounds__(128) k_head1(const float* __restrict__ wf1) {
    int t = threadIdx.x;
    const float4* wr = (const float4*)&wf1[(size_t)blockIdx.x * 1024];
    const float4* gr = (const float4*)d_g;
    float a = 0.f;
    for (int k = t; k < 256; k += 128) {
        float4 wv = __ldg(&wr[k]); float4 gv = gr[k];
        a += wv.x * gv.x + wv.y * gv.y + wv.z * gv.z + wv.w * gv.w;
    }
    float r = blk_dot_reduce(a);
    if (t == 0) d_f1[blockIdx.x] = fmaxf(r, 0.0f);
}

__global__ void __launch_bounds__(128) k_head2(const float* __restrict__ wf2) {
    int t = threadIdx.x;
    const float4* wr = (const float4*)&wf2[(size_t)blockIdx.x * 512];
    const float4* gr = (const float4*)d_f1;
    float a = 0.f;
    if (t < 128) {
        int k = t;  // 128 float4 = 512 floats
        float4 wv = __ldg(&wr[k]); float4 gv = gr[k];
        a = wv.x * gv.x + wv.y * gv.y + wv.z * gv.z + wv.w * gv.w;
    }
    float r = blk_dot_reduce(a);
    if (t == 0) d_f2[blockIdx.x] = fmaxf(r, 0.0f);
}

__global__ void __launch_bounds__(128) k_head3(const float* __restrict__ wf3,
                                               float* __restrict__ out) {
    int t = threadIdx.x;
    const float4* wr = (const float4*)&wf3[(size_t)blockIdx.x * 256];
    const float4* gr = (const float4*)d_f2;
    float a = 0.f;
    if (t < 64) {
        float4 wv = __ldg(&wr[t]); float4 gv = gr[t];
        a = wv.x * gv.x + wv.y * gv.y + wv.z * gv.z + wv.w * gv.w;
    }
    float r = blk_dot_reduce(a);
    if (t == 0) out[blockIdx.x] = r;
}

// ---------------- launch ----------------
extern "C" void kernel_launch(void* const* d_in, const int* in_sizes, int n_in,
                              void* d_out, int out_size) {
    const float* x       = (const float*)d_in[0];
    // d_in[1] = indptr: degree is fixed at K=16 (indptr = arange*16) -> unused
    const int*   indices = (const int*)d_in[2];
    const float* w1  = (const float*)d_in[3];
    const float* w2  = (const float*)d_in[4];
    const float* w3  = (const float*)d_in[5];
    const float* w4  = (const float*)d_in[6];
    const float* w5  = (const float*)d_in[7];
    const float* wf1 = (const float*)d_in[8];
    const float* wf2 = (const float*)d_in[9];
    const float* wf3 = (const float*)d_in[10];
    float* out = (float*)d_out;

    const int SMEM_A = (192 + 4096 + 256 * 66) * 4;           // 84,736 B
    const int SMEM_C = (128 * 130 + 128 * 68) * 4;            // 101,376 B
    const int SMEM_D = (64 * 196 + 192 * 64) * 4;             // 99,328 B
    cudaFuncSetAttribute(k_mlp12,   cudaFuncAttributeMaxDynamicSharedMemorySize, SMEM_A);
    cudaFuncSetAttribute(k_mlp34,   cudaFuncAttributeMaxDynamicSharedMemorySize, SMEM_C);
    cudaFuncSetAttribute(k_mlp5max, cudaFuncAttributeMaxDynamicSharedMemorySize, SMEM_D);

    k_zero_g<<<4, 256>>>();
    k_mlp12  <<<NPTS / 256, 256, SMEM_A>>>(x, w1, w2);
    k_gmax   <<<NPTS / 4,   256>>>(indices);
    k_mlp34  <<<NPTS / 128, 128, SMEM_C>>>(w3, w4);
    k_mlp5max<<<NPTS / 64,  256, SMEM_D>>>(w5);
    k_head1  <<<512, 128>>>(wf1);
    k_head2  <<<256, 128>>>(wf2);
    k_head3  <<<40,  128>>>(wf3, out);
}

// round 3
// speedup vs baseline: 2.8805x; 2.8805x over previous
#include <cuda_runtime.h>
#include <cstdint>

#define NPTS 262144

// ---------------- device scratch (no allocations allowed) ----------------
__device__ float d_h2 [NPTS * 64];       // after mlp1+mlp2 (relu)
__device__ float d_xgm[NPTS * 64];       // neighbor max-pooled (tf32-rounded)
__device__ float d_h4 [NPTS * 128];      // after mlp3+mlp4 (relu, tf32-rounded)
__device__ float d_w5r[1024 * 192];      // tf32-rounded copy of w5
__device__ float d_partial[2048 * 1024]; // per-rowtile per-col max (pre-relu)
__device__ float d_g  [1024];            // global max pooled features (post-relu)
__device__ float d_f1 [512];
__device__ float d_f2 [256];

// ---------------- helpers ----------------
__device__ __forceinline__ uint32_t smem_u32(const void* p) {
    uint32_t a;
    asm("{ .reg .u64 t; cvta.to.shared.u64 t, %1; cvt.u32.u64 %0, t; }"
        : "=r"(a) : "l"(p));
    return a;
}
__device__ __forceinline__ float to_tf32(float x) {   // round-to-nearest tf32
    float r;
    asm("cvt.rna.tf32.f32 %0, %1;" : "=f"(r) : "f"(x));
    return r;
}
__device__ __forceinline__ void cp16(uint32_t dst, const void* src) {
    asm volatile("cp.async.cg.shared.global [%0], [%1], 16;"
                 :: "r"(dst), "l"(src) : "memory");
}
#define CP_COMMIT() asm volatile("cp.async.commit_group;" ::: "memory")
#define CP_WAIT0()  asm volatile("cp.async.wait_group 0;" ::: "memory")

__device__ __forceinline__ void mma_tf32(float* c, const unsigned* a, const unsigned* b) {
    asm volatile(
        "mma.sync.aligned.m16n8k8.row.col.f32.tf32.tf32.f32 "
        "{%0,%1,%2,%3}, {%4,%5,%6,%7}, {%8,%9}, {%0,%1,%2,%3};"
        : "+f"(c[0]), "+f"(c[1]), "+f"(c[2]), "+f"(c[3])
        : "r"(a[0]), "r"(a[1]), "r"(a[2]), "r"(a[3]), "r"(b[0]), "r"(b[1]));
}

// ---------------- mlp1 + mlp2 : x[N,3] -> h2[N,64] ----------------
__global__ void __launch_bounds__(256) k_mlp12(const float* __restrict__ x,
                                               const float* __restrict__ w1,
                                               const float* __restrict__ w2) {
    extern __shared__ float sm[];
    float* s_w1  = sm;
    float* s_w2  = sm + 192;
    float* s_out = sm + 192 + 4096;

    int t = threadIdx.x;
    for (int i = t; i < 192;  i += 256) s_w1[i] = w1[i];
    for (int i = t; i < 4096; i += 256) s_w2[i] = w2[i];
    __syncthreads();

    int p = blockIdx.x * 256 + t;
    float x0 = x[p * 3 + 0], x1 = x[p * 3 + 1], x2 = x[p * 3 + 2];

    float h1[64];
#pragma unroll
    for (int j = 0; j < 64; j++) {
        float a = s_w1[j * 3 + 0] * x0 + s_w1[j * 3 + 1] * x1 + s_w1[j * 3 + 2] * x2;
        h1[j] = fmaxf(a, 0.0f);
    }

    for (int j = 0; j < 64; j++) {
        const float4* wr = (const float4*)&s_w2[j * 64];
        float a0 = 0.f, a1 = 0.f, a2 = 0.f, a3 = 0.f;
#pragma unroll
        for (int kk = 0; kk < 16; kk++) {
            float4 wv = wr[kk];
            a0 = fmaf(wv.x, h1[4 * kk + 0], a0);
            a1 = fmaf(wv.y, h1[4 * kk + 1], a1);
            a2 = fmaf(wv.z, h1[4 * kk + 2], a2);
            a3 = fmaf(wv.w, h1[4 * kk + 3], a3);
        }
        s_out[t * 66 + j] = fmaxf((a0 + a1) + (a2 + a3), 0.0f);
    }
    __syncthreads();

    size_t p0 = (size_t)blockIdx.x * 256;
    for (int i = t; i < 256 * 64; i += 256)
        d_h2[p0 * 64 + i] = s_out[(i >> 6) * 66 + (i & 63)];
}

// ---------------- graph max pooling (K=16), output tf32-rounded ----------------
__global__ void __launch_bounds__(256) k_gmax(const int* __restrict__ indices) {
    __shared__ int s_idx[4][16];
    int t  = threadIdx.x;
    int f  = t & 63;
    int pl = t >> 6;
    int p0 = blockIdx.x * 4;
    if (t < 64) s_idx[t >> 4][t & 15] = indices[p0 * 16 + t];
    __syncthreads();

    float m = 0.0f;
#pragma unroll
    for (int j = 0; j < 16; j++)
        m = fmaxf(m, d_h2[(size_t)s_idx[pl][j] * 64 + f]);

    d_xgm[(size_t)(p0 + pl) * 64 + f] = to_tf32(m);
}

// ---------------- mlp3 + mlp4 : h2[N,64] -> h4[N,128] (output tf32-rounded) ----------------
__global__ void __launch_bounds__(128) k_mlp34(const float* __restrict__ w3,
                                               const float* __restrict__ w4) {
    extern __shared__ float sb[];
    float* s_io = sb;
    float* s_h3 = sb + 128 * 130;

    int t = threadIdx.x;
    size_t p0 = (size_t)blockIdx.x * 128;

    for (int i = t; i < 128 * 64; i += 128)
        s_io[(i >> 6) * 68 + (i & 63)] = d_h2[p0 * 64 + i];
    __syncthreads();

    const float4* srow = (const float4*)&s_io[t * 68];
    for (int j = 0; j < 64; j++) {
        const float4* wr = (const float4*)&w3[j * 64];
        float a0 = 0.f, a1 = 0.f, a2 = 0.f, a3 = 0.f;
#pragma unroll
        for (int kk = 0; kk < 16; kk++) {
            float4 wv = __ldg(&wr[kk]);
            float4 sv = srow[kk];
            a0 = fmaf(wv.x, sv.x, a0);
            a1 = fmaf(wv.y, sv.y, a1);
            a2 = fmaf(wv.z, sv.z, a2);
            a3 = fmaf(wv.w, sv.w, a3);
        }
        s_h3[t * 68 + j] = fmaxf((a0 + a1) + (a2 + a3), 0.0f);
    }
    __syncthreads();

    const float4* hrow = (const float4*)&s_h3[t * 68];
    for (int j = 0; j < 128; j++) {
        const float4* wr = (const float4*)&w4[j * 64];
        float a0 = 0.f, a1 = 0.f, a2 = 0.f, a3 = 0.f;
#pragma unroll
        for (int kk = 0; kk < 16; kk++) {
            float4 wv = __ldg(&wr[kk]);
            float4 hv = hrow[kk];
            a0 = fmaf(wv.x, hv.x, a0);
            a1 = fmaf(wv.y, hv.y, a1);
            a2 = fmaf(wv.z, hv.z, a2);
            a3 = fmaf(wv.w, hv.w, a3);
        }
        s_io[t * 130 + j] = fmaxf((a0 + a1) + (a2 + a3), 0.0f);
    }
    __syncthreads();

    for (int i = t; i < 128 * 128; i += 128)
        d_h4[p0 * 128 + i] = to_tf32(s_io[(i >> 7) * 130 + (i & 127)]);
}

// ---------------- pre-round w5 to tf32 ----------------
__global__ void __launch_bounds__(256) k_prep_w5(const float* __restrict__ w5) {
    int i = blockIdx.x * 256 + threadIdx.x;       // float4 index, 49152 total
    float4 v = ((const float4*)w5)[i];
    v.x = to_tf32(v.x); v.y = to_tf32(v.y); v.z = to_tf32(v.z); v.w = to_tf32(v.w);
    ((float4*)d_w5r)[i] = v;
}

// ---------------- mlp5 + global max via mma.sync tf32 ----------------
// Block: 128 rows x 1024 cols (8 n-tiles of 128). A=[xgm||h4] tile in smem
// (stride 196, cp.async, loaded once). Per n-tile: B tile cp.async from
// pre-rounded d_w5r (L2-resident), 8 warps (2x4), warp tile 64x32, K=192 via
// 24 m16n8k8 tf32 K-steps. Col-max over rows fused in registers (h5 never
// materialized). Next B tile prefetched during the epilogue.
__global__ void __launch_bounds__(256) k_mlp5max() {
    extern __shared__ float sm[];
    float* s_a = sm;                 // 128 * 196
    float* s_b = sm + 128 * 196;     // 128 * 196
    __shared__ float s_red[8][32];

    int t    = threadIdx.x;
    int w    = t >> 5;
    int lane = t & 31;
    int g    = lane >> 2;            // 0..7
    int tig  = lane & 3;             // 0..3
    int wm   = w >> 2;               // 0..1  (row half)
    int wn   = w & 3;                // 0..3  (col quarter)
    size_t m0 = (size_t)blockIdx.x * 128;

    uint32_t a_base = smem_u32(s_a);
    uint32_t b_base = smem_u32(s_b);

    // stage A (once) + B tile 0
    for (int i = t; i < 128 * 48; i += 256) {
        int row = i / 48, c4 = i % 48;
        const float* src = (c4 < 16)
            ? &d_xgm[(m0 + row) * 64  + 4 * c4]
            : &d_h4 [(m0 + row) * 128 + 4 * c4 - 64];
        cp16(a_base + (uint32_t)(row * 196 + 4 * c4) * 4, src);
    }
    for (int i = t; i < 128 * 48; i += 256) {
        int row = i / 48, c4 = i % 48;
        cp16(b_base + (uint32_t)(row * 196 + 4 * c4) * 4,
             &d_w5r[(size_t)row * 192 + 4 * c4]);
    }
    CP_COMMIT();
    CP_WAIT0();
    __syncthreads();

    const float* pa = s_a + (wm * 64 + g) * 196 + tig;
    const float* pb = s_b + (wn * 32 + g) * 196 + tig;

    for (int nt = 0; nt < 8; nt++) {
        float c_[4][4][4];
#pragma unroll
        for (int i = 0; i < 4; i++)
#pragma unroll
            for (int j = 0; j < 4; j++)
#pragma unroll
                for (int r = 0; r < 4; r++) c_[i][j][r] = 0.0f;

#pragma unroll 4
        for (int s = 0; s < 24; s++) {
            int ko = s * 8;
            unsigned a_[4][4], b_[4][2];
#pragma unroll
            for (int mt = 0; mt < 4; mt++) {
                const float* p = pa + mt * (16 * 196) + ko;
                a_[mt][0] = __float_as_uint(p[0]);
                a_[mt][1] = __float_as_uint(p[8 * 196]);
                a_[mt][2] = __float_as_uint(p[4]);
                a_[mt][3] = __float_as_uint(p[8 * 196 + 4]);
            }
#pragma unroll
            for (int nq = 0; nq < 4; nq++) {
                const float* p = pb + nq * (8 * 196) + ko;
                b_[nq][0] = __float_as_uint(p[0]);
                b_[nq][1] = __float_as_uint(p[4]);
            }
#pragma unroll
            for (int mt = 0; mt < 4; mt++)
#pragma unroll
                for (int nq = 0; nq < 4; nq++)
                    mma_tf32(c_[mt][nq], a_[mt], b_[nq]);
        }

        __syncthreads();   // all warps done reading s_b

        if (nt < 7) {      // prefetch next B tile; overlaps the epilogue
            for (int i = t; i < 128 * 48; i += 256) {
                int row = i / 48, c4 = i % 48;
                cp16(b_base + (uint32_t)(row * 196 + 4 * c4) * 4,
                     &d_w5r[(size_t)((nt + 1) * 128 + row) * 192 + 4 * c4]);
            }
            CP_COMMIT();
        }

        // epilogue: col-max over this warp's 64 rows, then over the block
        float cm[8];
#pragma unroll
        for (int nq = 0; nq < 4; nq++) {
            float v0 = fmaxf(fmaxf(c_[0][nq][0], c_[0][nq][2]),
                             fmaxf(c_[1][nq][0], c_[1][nq][2]));
            v0 = fmaxf(v0, fmaxf(fmaxf(c_[2][nq][0], c_[2][nq][2]),
                                 fmaxf(c_[3][nq][0], c_[3][nq][2])));
            float v1 = fmaxf(fmaxf(c_[0][nq][1], c_[0][nq][3]),
                             fmaxf(c_[1][nq][1], c_[1][nq][3]));
            v1 = fmaxf(v1, fmaxf(fmaxf(c_[2][nq][1], c_[2][nq][3]),
                                 fmaxf(c_[3][nq][1], c_[3][nq][3])));
            cm[nq * 2 + 0] = v0;
            cm[nq * 2 + 1] = v1;
        }
#pragma unroll
        for (int off = 4; off < 32; off <<= 1)
#pragma unroll
            for (int j = 0; j < 8; j++)
                cm[j] = fmaxf(cm[j], __shfl_xor_sync(0xffffffffu, cm[j], off));
        if (lane < 4) {
#pragma unroll
            for (int nq = 0; nq < 4; nq++) {
                s_red[w][nq * 8 + lane * 2 + 0] = cm[nq * 2 + 0];
                s_red[w][nq * 8 + lane * 2 + 1] = cm[nq * 2 + 1];
            }
        }
        __syncthreads();
        if (t < 128) {
            float v = fmaxf(s_red[t >> 5][t & 31], s_red[4 + (t >> 5)][t & 31]);
            d_partial[(size_t)blockIdx.x * 1024 + nt * 128 + t] = v;
        }
        if (nt < 7) CP_WAIT0();
        __syncthreads();   // s_b / s_red safe for next iteration
    }
}

// ---------------- global reduce: d_partial[2048,1024] -> d_g[1024] (with relu) ----------------
__global__ void __launch_bounds__(256) k_greduce() {
    __shared__ float sr[8][32];
    int c  = blockIdx.x * 32 + (threadIdx.x & 31);
    int rg = threadIdx.x >> 5;
    float m = -1e30f;
#pragma unroll 4
    for (int b = rg * 256; b < rg * 256 + 256; b++)
        m = fmaxf(m, d_partial[(size_t)b * 1024 + c]);
    sr[rg][threadIdx.x & 31] = m;
    __syncthreads();
    if (threadIdx.x < 32) {
        float v = sr[0][threadIdx.x];
#pragma unroll
        for (int r = 1; r < 8; r++) v = fmaxf(v, sr[r][threadIdx.x]);
        d_g[blockIdx.x * 32 + threadIdx.x] = fmaxf(v, 0.0f);
    }
}

// ---------------- head: 3 small GEMVs ----------------
__device__ __forceinline__ float blk_dot_reduce(float a) {
#pragma unroll
    for (int o = 16; o; o >>= 1) a += __shfl_xor_sync(0xffffffffu, a, o);
    __shared__ float s[4];
    int t = threadIdx.x;
    if ((t & 31) == 0) s[t >> 5] = a;
    __syncthreads();
    return s[0] + s[1] + s[2] + s[3];
}

__global__ void __launch_bounds__(128) k_head1(const float* __restrict__ wf1) {
    int t = threadIdx.x;
    const float4* wr = (const float4*)&wf1[(size_t)blockIdx.x * 1024];
    const float4* gr = (const float4*)d_g;
    float a = 0.f;
    for (int k = t; k < 256; k += 128) {
        float4 wv = __ldg(&wr[k]); float4 gv = gr[k];
        a += wv.x * gv.x + wv.y * gv.y + wv.z * gv.z + wv.w * gv.w;
    }
    float r = blk_dot_reduce(a);
    if (t == 0) d_f1[blockIdx.x] = fmaxf(r, 0.0f);
}

__global__ void __launch_bounds__(128) k_head2(const float* __restrict__ wf2) {
    int t = threadIdx.x;
    const float4* wr = (const float4*)&wf2[(size_t)blockIdx.x * 512];
    const float4* gr = (const float4*)d_f1;
    float a = 0.f;
    if (t < 128) {
        float4 wv = __ldg(&wr[t]); float4 gv = gr[t];
        a = wv.x * gv.x + wv.y * gv.y + wv.z * gv.z + wv.w * gv.w;
    }
    float r = blk_dot_reduce(a);
    if (t == 0) d_f2[blockIdx.x] = fmaxf(r, 0.0f);
}

__global__ void __launch_bounds__(128) k_head3(const float* __restrict__ wf3,
                                               float* __restrict__ out) {
    int t = threadIdx.x;
    const float4* wr = (const float4*)&wf3[(size_t)blockIdx.x * 256];
    const float4* gr = (const float4*)d_f2;
    float a = 0.f;
    if (t < 64) {
        float4 wv = __ldg(&wr[t]); float4 gv = gr[t];
        a = wv.x * gv.x + wv.y * gv.y + wv.z * gv.z + wv.w * gv.w;
    }
    float r = blk_dot_reduce(a);
    if (t == 0) out[blockIdx.x] = r;
}

// ---------------- launch ----------------
extern "C" void kernel_launch(void* const* d_in, const int* in_sizes, int n_in,
                              void* d_out, int out_size) {
    const float* x       = (const float*)d_in[0];
    const int*   indices = (const int*)d_in[2];   // indptr (d_in[1]) is fixed K=16
    const float* w1  = (const float*)d_in[3];
    const float* w2  = (const float*)d_in[4];
    const float* w3  = (const float*)d_in[5];
    const float* w4  = (const float*)d_in[6];
    const float* w5  = (const float*)d_in[7];
    const float* wf1 = (const float*)d_in[8];
    const float* wf2 = (const float*)d_in[9];
    const float* wf3 = (const float*)d_in[10];
    float* out = (float*)d_out;

    const int SMEM_A = (192 + 4096 + 256 * 66) * 4;   // 84,736 B
    const int SMEM_C = (128 * 130 + 128 * 68) * 4;    // 101,376 B
    const int SMEM_G = 2 * 128 * 196 * 4;             // 200,704 B
    cudaFuncSetAttribute(k_mlp12,   cudaFuncAttributeMaxDynamicSharedMemorySize, SMEM_A);
    cudaFuncSetAttribute(k_mlp34,   cudaFuncAttributeMaxDynamicSharedMemorySize, SMEM_C);
    cudaFuncSetAttribute(k_mlp5max, cudaFuncAttributeMaxDynamicSharedMemorySize, SMEM_G);

    k_prep_w5<<<192, 256>>>(w5);
    k_mlp12  <<<NPTS / 256, 256, SMEM_A>>>(x, w1, w2);
    k_gmax   <<<NPTS / 4,   256>>>(indices);
    k_mlp34  <<<NPTS / 128, 128, SMEM_C>>>(w3, w4);
    k_mlp5max<<<NPTS / 128, 256, SMEM_G>>>();
    k_greduce<<<32, 256>>>();
    k_head1  <<<512, 128>>>(wf1);
    k_head2  <<<256, 128>>>(wf2);
    k_head3  <<<40,  128>>>(wf3, out);
}

// round 4
// speedup vs baseline: 12.0888x; 4.1967x over previous
#include <cuda_runtime.h>
#include <cuda_fp16.h>
#include <cstdint>

#define NPTS 262144

// ---------------- device scratch (no allocations allowed) ----------------
__device__ __half d_h2h [NPTS * 64];      // after mlp1+mlp2 (relu, fp16)
__device__ __half d_xgmh[NPTS * 64];      // neighbor max-pooled (fp16)
__device__ __half d_h4h [NPTS * 128];     // after mlp3+mlp4 (relu, fp16)
__device__ __half d_w3h [64 * 64];
__device__ __half d_w4h [128 * 64];
__device__ __half d_w5h [1024 * 192];
__device__ float  d_partial[2048 * 1024]; // per-rowtile per-col max (pre-relu)
__device__ float  d_g  [1024];
__device__ float  d_f1 [512];
__device__ float  d_f2 [256];

// ---------------- helpers ----------------
__device__ __forceinline__ uint32_t smem_u32(const void* p) {
    uint32_t a;
    asm("{ .reg .u64 t; cvta.to.shared.u64 t, %1; cvt.u32.u64 %0, t; }"
        : "=r"(a) : "l"(p));
    return a;
}
__device__ __forceinline__ void cp16(uint32_t dst, const void* src) {
    asm volatile("cp.async.cg.shared.global [%0], [%1], 16;"
                 :: "r"(dst), "l"(src) : "memory");
}
#define CP_COMMIT() asm volatile("cp.async.commit_group;" ::: "memory")
#define CP_WAIT0()  asm volatile("cp.async.wait_group 0;" ::: "memory")

__device__ __forceinline__ void ldsm4(uint32_t& r0, uint32_t& r1,
                                      uint32_t& r2, uint32_t& r3, uint32_t addr) {
    asm volatile("ldmatrix.sync.aligned.m8n8.x4.shared.b16 {%0,%1,%2,%3}, [%4];"
                 : "=r"(r0), "=r"(r1), "=r"(r2), "=r"(r3) : "r"(addr));
}
__device__ __forceinline__ void mma_f16(float* c, uint32_t a0, uint32_t a1,
                                        uint32_t a2, uint32_t a3,
                                        uint32_t b0, uint32_t b1) {
    asm volatile(
        "mma.sync.aligned.m16n8k16.row.col.f32.f16.f16.f32 "
        "{%0,%1,%2,%3}, {%4,%5,%6,%7}, {%8,%9}, {%0,%1,%2,%3};"
        : "+f"(c[0]), "+f"(c[1]), "+f"(c[2]), "+f"(c[3])
        : "r"(a0), "r"(a1), "r"(a2), "r"(a3), "r"(b0), "r"(b1));
}
__device__ __forceinline__ uint32_t ph2_relu(float x, float y) {
    __half2 h = __floats2half2_rn(fmaxf(x, 0.f), fmaxf(y, 0.f));
    return *reinterpret_cast<uint32_t*>(&h);
}

// ---------------- weight prep: fp32 -> fp16 ----------------
__global__ void __launch_bounds__(256) k_prep_w34(const float* __restrict__ w3,
                                                  const float* __restrict__ w4) {
    int i = blockIdx.x * 256 + threadIdx.x;   // 12288 total
    if (i < 4096)       d_w3h[i]        = __float2half_rn(w3[i]);
    else if (i < 12288) d_w4h[i - 4096] = __float2half_rn(w4[i - 4096]);
}
__global__ void __launch_bounds__(256) k_prep_w5(const float* __restrict__ w5) {
    int i = blockIdx.x * 256 + threadIdx.x;   // 196608 total
    d_w5h[i] = __float2half_rn(w5[i]);
}

// ---------------- mlp1 + mlp2 : x[N,3] -> h2[N,64] (fp32 math, fp16 store) ----------------
__global__ void __launch_bounds__(256) k_mlp12(const float* __restrict__ x,
                                               const float* __restrict__ w1,
                                               const float* __restrict__ w2) {
    extern __shared__ float sm[];
    float* s_w1  = sm;
    float* s_w2  = sm + 192;
    float* s_out = sm + 192 + 4096;

    int t = threadIdx.x;
    for (int i = t; i < 192;  i += 256) s_w1[i] = w1[i];
    for (int i = t; i < 4096; i += 256) s_w2[i] = w2[i];
    __syncthreads();

    int p = blockIdx.x * 256 + t;
    float x0 = x[p * 3 + 0], x1 = x[p * 3 + 1], x2 = x[p * 3 + 2];

    float h1[64];
#pragma unroll
    for (int j = 0; j < 64; j++) {
        float a = s_w1[j * 3 + 0] * x0 + s_w1[j * 3 + 1] * x1 + s_w1[j * 3 + 2] * x2;
        h1[j] = fmaxf(a, 0.0f);
    }

    for (int j = 0; j < 64; j++) {
        const float4* wr = (const float4*)&s_w2[j * 64];
        float a0 = 0.f, a1 = 0.f, a2 = 0.f, a3 = 0.f;
#pragma unroll
        for (int kk = 0; kk < 16; kk++) {
            float4 wv = wr[kk];
            a0 = fmaf(wv.x, h1[4 * kk + 0], a0);
            a1 = fmaf(wv.y, h1[4 * kk + 1], a1);
            a2 = fmaf(wv.z, h1[4 * kk + 2], a2);
            a3 = fmaf(wv.w, h1[4 * kk + 3], a3);
        }
        s_out[t * 66 + j] = fmaxf((a0 + a1) + (a2 + a3), 0.0f);
    }
    __syncthreads();

    size_t p0 = (size_t)blockIdx.x * 256;
    for (int i = t; i < 256 * 32; i += 256) {
        int row = i >> 5, c2 = i & 31;
        ((__half2*)d_h2h)[(p0 + row) * 32 + c2] =
            __floats2half2_rn(s_out[row * 66 + 2 * c2], s_out[row * 66 + 2 * c2 + 1]);
    }
}

// ---------------- graph max pooling (K=16), fp16, 32 threads/point ----------------
__global__ void __launch_bounds__(256) k_gmax(const int* __restrict__ indices) {
    __shared__ int s_idx[8][16];
    int t = threadIdx.x, lane = t & 31, pl = t >> 5;
    int base = blockIdx.x * 8;
    if (t < 128) s_idx[t >> 4][t & 15] = indices[base * 16 + t];
    __syncthreads();

    __half2 m = __float2half2_rn(0.0f);   // h2 >= 0
    const __half2* h2 = (const __half2*)d_h2h;
#pragma unroll
    for (int j = 0; j < 16; j++)
        m = __hmax2(m, h2[(size_t)s_idx[pl][j] * 32 + lane]);

    ((__half2*)d_xgmh)[(size_t)(base + pl) * 32 + lane] = m;
}

// ---------------- mlp3 + mlp4 via fp16 mma (h3 chained in registers) ----------------
// Block: 128 points, 8 warps, warp = 16 rows. GEMM1: [16x64]@w3^T (K=64),
// relu -> pack to A-fragments of GEMM2 (C-frag layout == A-frag layout),
// GEMM2: [16x128]@w4^T in two 64-col halves (keeps regs < 128 for 2 CTA/SM).
__global__ void __launch_bounds__(256, 2) k_mlp34() {
    extern __shared__ __half sh[];
    __half* s_out = sh + 23040;                // 128*136
    int t = threadIdx.x, lane = t & 31, w = t >> 5;
    int g = lane >> 2, tig = lane & 3;
    size_t p0 = (size_t)blockIdx.x * 128;
    uint32_t sb = smem_u32(sh);

    // stage h2 tile [128x64] (stride 72), w3 [64x64], w4 [128x64]
    for (int i = t; i < 1024; i += 256) {
        int r = i >> 3, c = i & 7;
        cp16(sb + (uint32_t)(r * 72 + c * 8) * 2, d_h2h + p0 * 64 + r * 64 + c * 8);
    }
    for (int i = t; i < 512; i += 256) {
        int r = i >> 3, c = i & 7;
        cp16(sb + (uint32_t)(9216 + r * 72 + c * 8) * 2, d_w3h + r * 64 + c * 8);
    }
    for (int i = t; i < 1024; i += 256) {
        int r = i >> 3, c = i & 7;
        cp16(sb + (uint32_t)(13824 + r * 72 + c * 8) * 2, d_w4h + r * 64 + c * 8);
    }
    CP_COMMIT(); CP_WAIT0();
    __syncthreads();

    // GEMM1: c1 = h2 @ w3^T  (M=16/warp, N=64, K=64)
    float c1[8][4];
#pragma unroll
    for (int j = 0; j < 8; j++)
#pragma unroll
        for (int r = 0; r < 4; r++) c1[j][r] = 0.f;

#pragma unroll
    for (int q = 0; q < 4; q++) {
        uint32_t A0, A1, A2, A3;
        uint32_t arow = 16 * w + (lane & 15);
        uint32_t ak   = q * 16 + 8 * (lane >> 4);
        ldsm4(A0, A1, A2, A3, sb + (arow * 72 + ak) * 2);
#pragma unroll
        for (int jp = 0; jp < 4; jp++) {
            uint32_t B0, B1, B2, B3;
            uint32_t bn = 16 * jp + (lane & 7) + 8 * (lane >> 4);
            uint32_t bk = q * 16 + 8 * ((lane >> 3) & 1);
            ldsm4(B0, B1, B2, B3, sb + (9216 + bn * 72 + bk) * 2);
            mma_f16(c1[2 * jp],     A0, A1, A2, A3, B0, B1);
            mma_f16(c1[2 * jp + 1], A0, A1, A2, A3, B2, B3);
        }
    }

    // relu + pack: GEMM2 A-fragments (k-chunk q from n8-tiles 2q, 2q+1)
    uint32_t a2[4][4];
#pragma unroll
    for (int q = 0; q < 4; q++) {
        a2[q][0] = ph2_relu(c1[2 * q][0],     c1[2 * q][1]);
        a2[q][1] = ph2_relu(c1[2 * q][2],     c1[2 * q][3]);
        a2[q][2] = ph2_relu(c1[2 * q + 1][0], c1[2 * q + 1][1]);
        a2[q][3] = ph2_relu(c1[2 * q + 1][2], c1[2 * q + 1][3]);
    }

    // GEMM2: h4 = relu(h3 @ w4^T), N=128 in two halves
#pragma unroll
    for (int nh = 0; nh < 2; nh++) {
        float c2[8][4];
#pragma unroll
        for (int j = 0; j < 8; j++)
#pragma unroll
            for (int r = 0; r < 4; r++) c2[j][r] = 0.f;
#pragma unroll
        for (int q = 0; q < 4; q++) {
#pragma unroll
            for (int jp = 0; jp < 4; jp++) {
                uint32_t B0, B1, B2, B3;
                uint32_t bn = 64 * nh + 16 * jp + (lane & 7) + 8 * (lane >> 4);
                uint32_t bk = q * 16 + 8 * ((lane >> 3) & 1);
                ldsm4(B0, B1, B2, B3, sb + (13824 + bn * 72 + bk) * 2);
                mma_f16(c2[2 * jp],     a2[q][0], a2[q][1], a2[q][2], a2[q][3], B0, B1);
                mma_f16(c2[2 * jp + 1], a2[q][0], a2[q][1], a2[q][2], a2[q][3], B2, B3);
            }
        }
#pragma unroll
        for (int j2 = 0; j2 < 8; j2++) {
            int coln = 64 * nh + 8 * j2 + 2 * tig;
            int r0 = 16 * w + g;
            *(uint32_t*)&s_out[r0 * 136 + coln]       = ph2_relu(c2[j2][0], c2[j2][1]);
            *(uint32_t*)&s_out[(r0 + 8) * 136 + coln] = ph2_relu(c2[j2][2], c2[j2][3]);
        }
    }
    __syncthreads();

    for (int i = t; i < 2048; i += 256) {
        int r = i >> 4, c = i & 15;
        uint4 v = *(uint4*)&s_out[r * 136 + c * 8];
        *(uint4*)&d_h4h[(p0 + r) * 128 + c * 8] = v;
    }
}

// ---------------- mlp5 + global max via fp16 mma + ldmatrix ----------------
// Block: 128 rows x 8 n-tiles of 128. A=[xgm||h4] fp16 tile (stride 200)
// loaded once; B tile cp.async-prefetched during epilogue. 8 warps (2x4),
// warp tile 64x32, K=192 = 12 m16n8k16 steps. Col-max fused in registers.
__global__ void __launch_bounds__(256, 2) k_mlp5max() {
    extern __shared__ __half sh5[];
    __half* s_a = sh5;             // 128*200
    __half* s_b = sh5 + 25600;     // 128*200
    __shared__ float s_red[8][32];

    int t = threadIdx.x, lane = t & 31, w = t >> 5;
    int wm = w >> 2, wn = w & 3;
    size_t m0 = (size_t)blockIdx.x * 128;
    uint32_t ab = smem_u32(s_a), bb = smem_u32(s_b);

    // stage A (once) + B tile 0
    for (int i = t; i < 3072; i += 256) {
        int r = i / 24, c = i % 24;
        const __half* src = (c < 8) ? d_xgmh + (m0 + r) * 64 + c * 8
                                    : d_h4h + (m0 + r) * 128 + (c - 8) * 8;
        cp16(ab + (uint32_t)(r * 200 + c * 8) * 2, src);
    }
    for (int i = t; i < 3072; i += 256) {
        int r = i / 24, c = i % 24;
        cp16(bb + (uint32_t)(r * 200 + c * 8) * 2, d_w5h + (size_t)r * 192 + c * 8);
    }
    CP_COMMIT(); CP_WAIT0();
    __syncthreads();

    for (int nt = 0; nt < 8; nt++) {
        float c_[4][4][4];
#pragma unroll
        for (int i = 0; i < 4; i++)
#pragma unroll
            for (int j = 0; j < 4; j++)
#pragma unroll
                for (int r = 0; r < 4; r++) c_[i][j][r] = 0.f;

#pragma unroll
        for (int q = 0; q < 12; q++) {
            uint32_t a_[4][4], b_[2][4];
#pragma unroll
            for (int mt = 0; mt < 4; mt++) {
                uint32_t row = 64 * wm + 16 * mt + (lane & 15);
                uint32_t kh  = q * 16 + 8 * (lane >> 4);
                ldsm4(a_[mt][0], a_[mt][1], a_[mt][2], a_[mt][3],
                      ab + (row * 200 + kh) * 2);
            }
#pragma unroll
            for (int p = 0; p < 2; p++) {
                uint32_t bn = 32 * wn + 16 * p + (lane & 7) + 8 * (lane >> 4);
                uint32_t kh = q * 16 + 8 * ((lane >> 3) & 1);
                ldsm4(b_[p][0], b_[p][1], b_[p][2], b_[p][3],
                      bb + (bn * 200 + kh) * 2);
            }
#pragma unroll
            for (int mt = 0; mt < 4; mt++) {
                mma_f16(c_[mt][0], a_[mt][0], a_[mt][1], a_[mt][2], a_[mt][3], b_[0][0], b_[0][1]);
                mma_f16(c_[mt][1], a_[mt][0], a_[mt][1], a_[mt][2], a_[mt][3], b_[0][2], b_[0][3]);
                mma_f16(c_[mt][2], a_[mt][0], a_[mt][1], a_[mt][2], a_[mt][3], b_[1][0], b_[1][1]);
                mma_f16(c_[mt][3], a_[mt][0], a_[mt][1], a_[mt][2], a_[mt][3], b_[1][2], b_[1][3]);
            }
        }

        __syncthreads();   // all warps done reading s_b

        if (nt < 7) {      // prefetch next B tile; overlaps epilogue
            for (int i = t; i < 3072; i += 256) {
                int r = i / 24, c = i % 24;
                cp16(bb + (uint32_t)(r * 200 + c * 8) * 2,
                     d_w5h + (size_t)((nt + 1) * 128 + r) * 192 + c * 8);
            }
            CP_COMMIT();
        }

        // epilogue: col-max over this warp's 64 rows, then block-wide
        float cm[8];
#pragma unroll
        for (int nq = 0; nq < 4; nq++) {
            float v0 = fmaxf(fmaxf(c_[0][nq][0], c_[0][nq][2]),
                             fmaxf(c_[1][nq][0], c_[1][nq][2]));
            v0 = fmaxf(v0, fmaxf(fmaxf(c_[2][nq][0], c_[2][nq][2]),
                                 fmaxf(c_[3][nq][0], c_[3][nq][2])));
            float v1 = fmaxf(fmaxf(c_[0][nq][1], c_[0][nq][3]),
                             fmaxf(c_[1][nq][1], c_[1][nq][3]));
            v1 = fmaxf(v1, fmaxf(fmaxf(c_[2][nq][1], c_[2][nq][3]),
                                 fmaxf(c_[3][nq][1], c_[3][nq][3])));
            cm[nq * 2 + 0] = v0;
            cm[nq * 2 + 1] = v1;
        }
#pragma unroll
        for (int off = 4; off < 32; off <<= 1)
#pragma unroll
            for (int j = 0; j < 8; j++)
                cm[j] = fmaxf(cm[j], __shfl_xor_sync(0xffffffffu, cm[j], off));
        if (lane < 4) {
#pragma unroll
            for (int nq = 0; nq < 4; nq++) {
                s_red[w][nq * 8 + lane * 2 + 0] = cm[nq * 2 + 0];
                s_red[w][nq * 8 + lane * 2 + 1] = cm[nq * 2 + 1];
            }
        }
        __syncthreads();
        if (t < 128) {
            float v = fmaxf(s_red[t >> 5][t & 31], s_red[4 + (t >> 5)][t & 31]);
            d_partial[(size_t)blockIdx.x * 1024 + nt * 128 + t] = v;
        }
        if (nt < 7) CP_WAIT0();
        __syncthreads();
    }
}

// ---------------- global reduce: d_partial[2048,1024] -> d_g[1024] (relu) ----------------
__global__ void __launch_bounds__(256) k_greduce() {
    __shared__ float sr[8][32];
    int c  = blockIdx.x * 32 + (threadIdx.x & 31);
    int rg = threadIdx.x >> 5;
    float m = -1e30f;
#pragma unroll 4
    for (int b = rg * 256; b < rg * 256 + 256; b++)
        m = fmaxf(m, d_partial[(size_t)b * 1024 + c]);
    sr[rg][threadIdx.x & 31] = m;
    __syncthreads();
    if (threadIdx.x < 32) {
        float v = sr[0][threadIdx.x];
#pragma unroll
        for (int r = 1; r < 8; r++) v = fmaxf(v, sr[r][threadIdx.x]);
        d_g[blockIdx.x * 32 + threadIdx.x] = fmaxf(v, 0.0f);
    }
}

// ---------------- head: 3 small GEMVs ----------------
__device__ __forceinline__ float blk_dot_reduce(float a) {
#pragma unroll
    for (int o = 16; o; o >>= 1) a += __shfl_xor_sync(0xffffffffu, a, o);
    __shared__ float s[4];
    int t = threadIdx.x;
    if ((t & 31) == 0) s[t >> 5] = a;
    __syncthreads();
    return s[0] + s[1] + s[2] + s[3];
}

__global__ void __launch_bounds__(128) k_head1(const float* __restrict__ wf1) {
    int t = threadIdx.x;
    const float4* wr = (const float4*)&wf1[(size_t)blockIdx.x * 1024];
    const float4* gr = (const float4*)d_g;
    float a = 0.f;
    for (int k = t; k < 256; k += 128) {
        float4 wv = __ldg(&wr[k]); float4 gv = gr[k];
        a += wv.x * gv.x + wv.y * gv.y + wv.z * gv.z + wv.w * gv.w;
    }
    float r = blk_dot_reduce(a);
    if (t == 0) d_f1[blockIdx.x] = fmaxf(r, 0.0f);
}

__global__ void __launch_bounds__(128) k_head2(const float* __restrict__ wf2) {
    int t = threadIdx.x;
    const float4* wr = (const float4*)&wf2[(size_t)blockIdx.x * 512];
    const float4* gr = (const float4*)d_f1;
    float a = 0.f;
    if (t < 128) {
        float4 wv = __ldg(&wr[t]); float4 gv = gr[t];
        a = wv.x * gv.x + wv.y * gv.y + wv.z * gv.z + wv.w * gv.w;
    }
    float r = blk_dot_reduce(a);
    if (t == 0) d_f2[blockIdx.x] = fmaxf(r, 0.0f);
}

__global__ void __launch_bounds__(128) k_head3(const float* __restrict__ wf3,
                                               float* __restrict__ out) {
    int t = threadIdx.x;
    const float4* wr = (const float4*)&wf3[(size_t)blockIdx.x * 256];
    const float4* gr = (const float4*)d_f2;
    float a = 0.f;
    if (t < 64) {
        float4 wv = __ldg(&wr[t]); float4 gv = gr[t];
        a = wv.x * gv.x + wv.y * gv.y + wv.z * gv.z + wv.w * gv.w;
    }
    float r = blk_dot_reduce(a);
    if (t == 0) out[blockIdx.x] = r;
}

// ---------------- launch ----------------
extern "C" void kernel_launch(void* const* d_in, const int* in_sizes, int n_in,
                              void* d_out, int out_size) {
    const float* x       = (const float*)d_in[0];
    const int*   indices = (const int*)d_in[2];   // indptr (d_in[1]) fixed K=16
    const float* w1  = (const float*)d_in[3];
    const float* w2  = (const float*)d_in[4];
    const float* w3  = (const float*)d_in[5];
    const float* w4  = (const float*)d_in[6];
    const float* w5  = (const float*)d_in[7];
    const float* wf1 = (const float*)d_in[8];
    const float* wf2 = (const float*)d_in[9];
    const float* wf3 = (const float*)d_in[10];
    float* out = (float*)d_out;

    const int SMEM_A  = (192 + 4096 + 256 * 66) * 4;  // 84,736 B
    const int SMEM_34 = (23040 + 128 * 136) * 2;      // 80,896 B
    const int SMEM_5  = 2 * 128 * 200 * 2;            // 102,400 B
    cudaFuncSetAttribute(k_mlp12,   cudaFuncAttributeMaxDynamicSharedMemorySize, SMEM_A);
    cudaFuncSetAttribute(k_mlp34,   cudaFuncAttributeMaxDynamicSharedMemorySize, SMEM_34);
    cudaFuncSetAttribute(k_mlp5max, cudaFuncAttributeMaxDynamicSharedMemorySize, SMEM_5);

    k_prep_w34<<<48,  256>>>(w3, w4);
    k_prep_w5 <<<768, 256>>>(w5);
    k_mlp12  <<<NPTS / 256, 256, SMEM_A>>>(x, w1, w2);
    k_gmax   <<<NPTS / 8,   256>>>(indices);
    k_mlp34  <<<NPTS / 128, 256, SMEM_34>>>();
    k_mlp5max<<<NPTS / 128, 256, SMEM_5>>>();
    k_greduce<<<32, 256>>>();
    k_head1  <<<512, 128>>>(wf1);
    k_head2  <<<256, 128>>>(wf2);
    k_head3  <<<40,  128>>>(wf3, out);
}

// round 5
// speedup vs baseline: 14.7148x; 1.2172x over previous
#include <cuda_runtime.h>
#include <cuda_fp16.h>
#include <cstdint>

#define NPTS 262144

// ---------------- device scratch (no allocations allowed) ----------------
__device__ __half d_h2h [NPTS * 64];      // after mlp1+mlp2 (relu, fp16)
__device__ __half d_xgmh[NPTS * 64];      // neighbor max-pooled (fp16)
__device__ __half d_h4h [NPTS * 128];     // after mlp3+mlp4 (relu, fp16)
__device__ __half d_w2h [64 * 64];
__device__ __half d_w3h [64 * 64];
__device__ __half d_w4h [128 * 64];
__device__ __half d_w5h [1024 * 192];
__device__ float  d_partial[1024 * 1024]; // per-rowtile per-col max (pre-relu)
__device__ float  d_g  [1024];
__device__ float  d_f1 [512];
__device__ float  d_f2 [256];

// ---------------- helpers ----------------
__device__ __forceinline__ uint32_t smem_u32(const void* p) {
    uint32_t a;
    asm("{ .reg .u64 t; cvta.to.shared.u64 t, %1; cvt.u32.u64 %0, t; }"
        : "=r"(a) : "l"(p));
    return a;
}
__device__ __forceinline__ void cp16(uint32_t dst, const void* src) {
    asm volatile("cp.async.cg.shared.global [%0], [%1], 16;"
                 :: "r"(dst), "l"(src) : "memory");
}
#define CP_COMMIT() asm volatile("cp.async.commit_group;" ::: "memory")
#define CP_WAIT0()  asm volatile("cp.async.wait_group 0;" ::: "memory")
#define CP_WAIT1()  asm volatile("cp.async.wait_group 1;" ::: "memory")

__device__ __forceinline__ void ldsm4(uint32_t& r0, uint32_t& r1,
                                      uint32_t& r2, uint32_t& r3, uint32_t addr) {
    asm volatile("ldmatrix.sync.aligned.m8n8.x4.shared.b16 {%0,%1,%2,%3}, [%4];"
                 : "=r"(r0), "=r"(r1), "=r"(r2), "=r"(r3) : "r"(addr));
}
__device__ __forceinline__ void mma_f16(float* c, uint32_t a0, uint32_t a1,
                                        uint32_t a2, uint32_t a3,
                                        uint32_t b0, uint32_t b1) {
    asm volatile(
        "mma.sync.aligned.m16n8k16.row.col.f32.f16.f16.f32 "
        "{%0,%1,%2,%3}, {%4,%5,%6,%7}, {%8,%9}, {%0,%1,%2,%3};"
        : "+f"(c[0]), "+f"(c[1]), "+f"(c[2]), "+f"(c[3])
        : "r"(a0), "r"(a1), "r"(a2), "r"(a3), "r"(b0), "r"(b1));
}
__device__ __forceinline__ uint32_t ph2_relu(float x, float y) {
    __half2 h = __floats2half2_rn(fmaxf(x, 0.f), fmaxf(y, 0.f));
    return *reinterpret_cast<uint32_t*>(&h);
}

// B stationed in smem rows [n x 72-stride]; GEMM over K=64, N=64
__device__ __forceinline__ void gemm64(uint32_t sbase, const uint32_t (&a)[4][4],
                                       float (&c)[8][4], int lane) {
#pragma unroll
    for (int j = 0; j < 8; j++)
#pragma unroll
        for (int r = 0; r < 4; r++) c[j][r] = 0.f;
#pragma unroll
    for (int q = 0; q < 4; q++) {
#pragma unroll
        for (int jp = 0; jp < 4; jp++) {
            uint32_t B0, B1, B2, B3;
            uint32_t bn = 16 * jp + (lane & 7) + 8 * (lane >> 4);
            uint32_t bk = q * 16 + 8 * ((lane >> 3) & 1);
            ldsm4(B0, B1, B2, B3, sbase + (bn * 72 + bk) * 2);
            mma_f16(c[2 * jp],     a[q][0], a[q][1], a[q][2], a[q][3], B0, B1);
            mma_f16(c[2 * jp + 1], a[q][0], a[q][1], a[q][2], a[q][3], B2, B3);
        }
    }
}
__device__ __forceinline__ void pack_relu(const float (&c)[8][4], uint32_t (&a)[4][4]) {
#pragma unroll
    for (int q = 0; q < 4; q++) {
        a[q][0] = ph2_relu(c[2 * q][0],     c[2 * q][1]);
        a[q][1] = ph2_relu(c[2 * q][2],     c[2 * q][3]);
        a[q][2] = ph2_relu(c[2 * q + 1][0], c[2 * q + 1][1]);
        a[q][3] = ph2_relu(c[2 * q + 1][2], c[2 * q + 1][3]);
    }
}

// ---------------- weight prep: fp32 -> fp16 (w2, w3, w4) ----------------
__global__ void __launch_bounds__(256) k_prep_w(const float* __restrict__ w2,
                                                const float* __restrict__ w3,
                                                const float* __restrict__ w4) {
    int i = blockIdx.x * 256 + threadIdx.x;   // 16384 total
    if (i < 4096)       d_w2h[i]        = __float2half_rn(w2[i]);
    else if (i < 8192)  d_w3h[i - 4096] = __float2half_rn(w3[i - 4096]);
    else                d_w4h[i - 8192] = __float2half_rn(w4[i - 8192]);
}
__global__ void __launch_bounds__(256) k_prep_w5(const float* __restrict__ w5) {
    int i = blockIdx.x * 256 + threadIdx.x;   // 196608 total
    d_w5h[i] = __float2half_rn(w5[i]);
}

// ---------------- fused mlp1..mlp4 : x[N,3] -> h2[N,64], h4[N,128] ----------------
// Block: 128 points, 8 warps x 16 rows. mlp1 computed scalar-fp32 directly into
// A-fragment layout; GEMM2/3/4 chained in registers (c-frag -> a-frag repack).
__global__ void __launch_bounds__(256, 2) k_mlp1234(const float* __restrict__ x,
                                                    const float* __restrict__ w1) {
    extern __shared__ __half sh[];
    const int OFF_W2 = 0, OFF_W3 = 4608, OFF_W4 = 9216, OFF_OUT = 18432;
    __half* s_out = sh + OFF_OUT;                   // 128*136
    float*  s_xf  = (float*)(sh + 35840);           // 128*3
    float*  s_w1f = s_xf + 384;                     // 64*3

    int t = threadIdx.x, lane = t & 31, w = t >> 5;
    int g = lane >> 2, tig = lane & 3;
    size_t p0 = (size_t)blockIdx.x * 128;
    uint32_t sb = smem_u32(sh);

    // stage weights (fp16, stride 72) via cp.async
    for (int i = t; i < 512; i += 256) {
        int r = i >> 3, c = i & 7;
        cp16(sb + (uint32_t)(OFF_W2 + r * 72 + c * 8) * 2, d_w2h + r * 64 + c * 8);
        cp16(sb + (uint32_t)(OFF_W3 + r * 72 + c * 8) * 2, d_w3h + r * 64 + c * 8);
    }
    for (int i = t; i < 1024; i += 256) {
        int r = i >> 3, c = i & 7;
        cp16(sb + (uint32_t)(OFF_W4 + r * 72 + c * 8) * 2, d_w4h + r * 64 + c * 8);
    }
    // x tile + w1 (fp32)
    for (int i = t; i < 384; i += 256) s_xf[i] = x[p0 * 3 + i];
    if (t < 192) s_w1f[t] = w1[t];
    CP_COMMIT(); CP_WAIT0();
    __syncthreads();

    // mlp1: compute this thread's 32 h1 values straight into a-frag layout
    int r0 = 16 * w + g;
    float xa0 = s_xf[r0 * 3], xa1 = s_xf[r0 * 3 + 1], xa2 = s_xf[r0 * 3 + 2];
    float xb0 = s_xf[(r0 + 8) * 3], xb1 = s_xf[(r0 + 8) * 3 + 1], xb2 = s_xf[(r0 + 8) * 3 + 2];
    uint32_t a1h[4][4];
#pragma unroll
    for (int q = 0; q < 4; q++) {
        int f0 = 16 * q + 2 * tig;
        int f2 = f0 + 8;
#define DOT3(f, u0, u1, u2) \
        fmaf(s_w1f[(f)*3+2], u2, fmaf(s_w1f[(f)*3+1], u1, s_w1f[(f)*3] * u0))
        a1h[q][0] = ph2_relu(DOT3(f0, xa0, xa1, xa2), DOT3(f0 + 1, xa0, xa1, xa2));
        a1h[q][1] = ph2_relu(DOT3(f0, xb0, xb1, xb2), DOT3(f0 + 1, xb0, xb1, xb2));
        a1h[q][2] = ph2_relu(DOT3(f2, xa0, xa1, xa2), DOT3(f2 + 1, xa0, xa1, xa2));
        a1h[q][3] = ph2_relu(DOT3(f2, xb0, xb1, xb2), DOT3(f2 + 1, xb0, xb1, xb2));
#undef DOT3
    }

    // GEMM2: h2 = relu(h1 @ w2^T)
    float c2[8][4];
    uint32_t a2h[4][4];
    gemm64(sb + OFF_W2 * 2, a1h, c2, lane);
    pack_relu(c2, a2h);

    // stage h2 -> s_out, then coalesced global store
#pragma unroll
    for (int q = 0; q < 4; q++) {
        int c0 = 16 * q + 2 * tig, cc2 = c0 + 8;
        *(uint32_t*)&s_out[r0 * 136 + c0]        = a2h[q][0];
        *(uint32_t*)&s_out[(r0 + 8) * 136 + c0]  = a2h[q][1];
        *(uint32_t*)&s_out[r0 * 136 + cc2]       = a2h[q][2];
        *(uint32_t*)&s_out[(r0 + 8) * 136 + cc2] = a2h[q][3];
    }
    __syncthreads();
    for (int i = t; i < 1024; i += 256) {
        int r = i >> 3, c = i & 7;
        *(uint4*)&d_h2h[(p0 + r) * 64 + c * 8] = *(uint4*)&s_out[r * 136 + c * 8];
    }
    __syncthreads();   // s_out reused for h4

    // GEMM3: h3 = relu(h2 @ w3^T)
    float c3[8][4];
    uint32_t a3h[4][4];
    gemm64(sb + OFF_W3 * 2, a2h, c3, lane);
    pack_relu(c3, a3h);

    // GEMM4: h4 = relu(h3 @ w4^T), N=128 in two halves
#pragma unroll
    for (int nh = 0; nh < 2; nh++) {
        float c4[8][4];
#pragma unroll
        for (int j = 0; j < 8; j++)
#pragma unroll
            for (int r = 0; r < 4; r++) c4[j][r] = 0.f;
#pragma unroll
        for (int q = 0; q < 4; q++) {
#pragma unroll
            for (int jp = 0; jp < 4; jp++) {
                uint32_t B0, B1, B2, B3;
                uint32_t bn = 64 * nh + 16 * jp + (lane & 7) + 8 * (lane >> 4);
                uint32_t bk = q * 16 + 8 * ((lane >> 3) & 1);
                ldsm4(B0, B1, B2, B3, sb + (OFF_W4 + bn * 72 + bk) * 2);
                mma_f16(c4[2 * jp],     a3h[q][0], a3h[q][1], a3h[q][2], a3h[q][3], B0, B1);
                mma_f16(c4[2 * jp + 1], a3h[q][0], a3h[q][1], a3h[q][2], a3h[q][3], B2, B3);
            }
        }
#pragma unroll
        for (int j2 = 0; j2 < 8; j2++) {
            int coln = 64 * nh + 8 * j2 + 2 * tig;
            *(uint32_t*)&s_out[r0 * 136 + coln]       = ph2_relu(c4[j2][0], c4[j2][1]);
            *(uint32_t*)&s_out[(r0 + 8) * 136 + coln] = ph2_relu(c4[j2][2], c4[j2][3]);
        }
    }
    __syncthreads();
    for (int i = t; i < 2048; i += 256) {
        int r = i >> 4, c = i & 15;
        *(uint4*)&d_h4h[(p0 + r) * 128 + c * 8] = *(uint4*)&s_out[r * 136 + c * 8];
    }
}

// ---------------- graph max pooling (K=16), fp16, 32 threads/point ----------------
__global__ void __launch_bounds__(256) k_gmax(const int* __restrict__ indices) {
    __shared__ int s_idx[8][16];
    int t = threadIdx.x, lane = t & 31, pl = t >> 5;
    int base = blockIdx.x * 8;
    if (t < 128) s_idx[t >> 4][t & 15] = indices[base * 16 + t];
    __syncthreads();

    __half2 m = __float2half2_rn(0.0f);   // h2 >= 0
    const __half2* h2 = (const __half2*)d_h2h;
#pragma unroll
    for (int j = 0; j < 16; j++) {
        unsigned off = (unsigned)s_idx[pl][j] * 32u + (unsigned)lane;  // 32-bit addr math
        m = __hmax2(m, h2[off]);
    }
    ((__half2*)d_xgmh)[(unsigned)(base + pl) * 32u + lane] = m;
}

// ---------------- mlp5 + global max : 256-row blocks, double-buffered B ----------------
__global__ void __launch_bounds__(512) k_mlp5max() {
    extern __shared__ __half sh5[];
    __half* s_a = sh5;                        // 256*200
    __shared__ float s_red[16][32];

    int t = threadIdx.x, lane = t & 31, w = t >> 5;
    int wm = w >> 2, wn = w & 3;
    size_t m0 = (size_t)blockIdx.x * 256;
    uint32_t ab = smem_u32(s_a);
    uint32_t bb0 = ab + 51200 * 2, bb1 = ab + 76800 * 2;

    // stage A (once): 256 rows x 24 16B-chunks
    for (int i = t; i < 6144; i += 512) {
        int r = i / 24, c = i % 24;
        const __half* src = (c < 8) ? d_xgmh + (m0 + r) * 64 + c * 8
                                    : d_h4h + (m0 + r) * 128 + (c - 8) * 8;
        cp16(ab + (uint32_t)(r * 200 + c * 8) * 2, src);
    }
    for (int i = t; i < 3072; i += 512) {
        int r = i / 24, c = i % 24;
        cp16(bb0 + (uint32_t)(r * 200 + c * 8) * 2, d_w5h + (size_t)r * 192 + c * 8);
    }
    CP_COMMIT();
    for (int i = t; i < 3072; i += 512) {
        int r = i / 24, c = i % 24;
        cp16(bb1 + (uint32_t)(r * 200 + c * 8) * 2, d_w5h + (size_t)(128 + r) * 192 + c * 8);
    }
    CP_COMMIT();

    for (int nt = 0; nt < 8; nt++) {
        CP_WAIT1();          // current buffer's group done (<=1 pending)
        __syncthreads();
        uint32_t cur = (nt & 1) ? bb1 : bb0;

        float c_[4][4][4];
#pragma unroll
        for (int i = 0; i < 4; i++)
#pragma unroll
            for (int j = 0; j < 4; j++)
#pragma unroll
                for (int r = 0; r < 4; r++) c_[i][j][r] = 0.f;

#pragma unroll
        for (int q = 0; q < 12; q++) {
            uint32_t a_[4][4], b_[2][4];
#pragma unroll
            for (int mt = 0; mt < 4; mt++) {
                uint32_t row = 64 * wm + 16 * mt + (lane & 15);
                uint32_t kh  = q * 16 + 8 * (lane >> 4);
                ldsm4(a_[mt][0], a_[mt][1], a_[mt][2], a_[mt][3],
                      ab + (row * 200 + kh) * 2);
            }
#pragma unroll
            for (int p = 0; p < 2; p++) {
                uint32_t bn = 32 * wn + 16 * p + (lane & 7) + 8 * (lane >> 4);
                uint32_t kh = q * 16 + 8 * ((lane >> 3) & 1);
                ldsm4(b_[p][0], b_[p][1], b_[p][2], b_[p][3],
                      cur + (bn * 200 + kh) * 2);
            }
#pragma unroll
            for (int mt = 0; mt < 4; mt++) {
                mma_f16(c_[mt][0], a_[mt][0], a_[mt][1], a_[mt][2], a_[mt][3], b_[0][0], b_[0][1]);
                mma_f16(c_[mt][1], a_[mt][0], a_[mt][1], a_[mt][2], a_[mt][3], b_[0][2], b_[0][3]);
                mma_f16(c_[mt][2], a_[mt][0], a_[mt][1], a_[mt][2], a_[mt][3], b_[1][0], b_[1][1]);
                mma_f16(c_[mt][3], a_[mt][0], a_[mt][1], a_[mt][2], a_[mt][3], b_[1][2], b_[1][3]);
            }
        }
        __syncthreads();     // all warps done reading cur

        if (nt < 6) {        // prefetch nt+2 into the buffer just freed
            uint32_t nxt = (nt & 1) ? bb1 : bb0;
            for (int i = t; i < 3072; i += 512) {
                int r = i / 24, c = i % 24;
                cp16(nxt + (uint32_t)(r * 200 + c * 8) * 2,
                     d_w5h + (size_t)((nt + 2) * 128 + r) * 192 + c * 8);
            }
            CP_COMMIT();
        }

        // epilogue: col-max over this warp's 64 rows, then block-wide over 256
        float cm[8];
#pragma unroll
        for (int nq = 0; nq < 4; nq++) {
            float v0 = fmaxf(fmaxf(c_[0][nq][0], c_[0][nq][2]),
                             fmaxf(c_[1][nq][0], c_[1][nq][2]));
            v0 = fmaxf(v0, fmaxf(fmaxf(c_[2][nq][0], c_[2][nq][2]),
                                 fmaxf(c_[3][nq][0], c_[3][nq][2])));
            float v1 = fmaxf(fmaxf(c_[0][nq][1], c_[0][nq][3]),
                             fmaxf(c_[1][nq][1], c_[1][nq][3]));
            v1 = fmaxf(v1, fmaxf(fmaxf(c_[2][nq][1], c_[2][nq][3]),
                                 fmaxf(c_[3][nq][1], c_[3][nq][3])));
            cm[nq * 2 + 0] = v0;
            cm[nq * 2 + 1] = v1;
        }
#pragma unroll
        for (int off = 4; off < 32; off <<= 1)
#pragma unroll
            for (int j = 0; j < 8; j++)
                cm[j] = fmaxf(cm[j], __shfl_xor_sync(0xffffffffu, cm[j], off));
        if (lane < 4) {
#pragma unroll
            for (int nq = 0; nq < 4; nq++) {
                s_red[w][nq * 8 + lane * 2 + 0] = cm[nq * 2 + 0];
                s_red[w][nq * 8 + lane * 2 + 1] = cm[nq * 2 + 1];
            }
        }
        __syncthreads();
        if (t < 128) {
            int grp = t >> 5, c = t & 31;
            float v = fmaxf(fmaxf(s_red[grp][c], s_red[4 + grp][c]),
                            fmaxf(s_red[8 + grp][c], s_red[12 + grp][c]));
            d_partial[(size_t)blockIdx.x * 1024 + nt * 128 + t] = v;
        }
    }
}

// ---------------- global reduce: d_partial[1024,1024] -> d_g[1024] (relu) ----------------
__global__ void __launch_bounds__(256) k_greduce() {
    __shared__ float sr[8][32];
    int c  = blockIdx.x * 32 + (threadIdx.x & 31);
    int rg = threadIdx.x >> 5;
    float m = -1e30f;
#pragma unroll 4
    for (int b = rg * 128; b < rg * 128 + 128; b++)
        m = fmaxf(m, d_partial[(size_t)b * 1024 + c]);
    sr[rg][threadIdx.x & 31] = m;
    __syncthreads();
    if (threadIdx.x < 32) {
        float v = sr[0][threadIdx.x];
#pragma unroll
        for (int r = 1; r < 8; r++) v = fmaxf(v, sr[r][threadIdx.x]);
        d_g[blockIdx.x * 32 + threadIdx.x] = fmaxf(v, 0.0f);
    }
}

// ---------------- head: 3 small GEMVs ----------------
__device__ __forceinline__ float blk_dot_reduce(float a) {
#pragma unroll
    for (int o = 16; o; o >>= 1) a += __shfl_xor_sync(0xffffffffu, a, o);
    __shared__ float s[4];
    int t = threadIdx.x;
    if ((t & 31) == 0) s[t >> 5] = a;
    __syncthreads();
    return s[0] + s[1] + s[2] + s[3];
}

__global__ void __launch_bounds__(128) k_head1(const float* __restrict__ wf1) {
    int t = threadIdx.x;
    const float4* wr = (const float4*)&wf1[(size_t)blockIdx.x * 1024];
    const float4* gr = (const float4*)d_g;
    float a = 0.f;
    for (int k = t; k < 256; k += 128) {
        float4 wv = __ldg(&wr[k]); float4 gv = gr[k];
        a += wv.x * gv.x + wv.y * gv.y + wv.z * gv.z + wv.w * gv.w;
    }
    float r = blk_dot_reduce(a);
    if (t == 0) d_f1[blockIdx.x] = fmaxf(r, 0.0f);
}

__global__ void __launch_bounds__(128) k_head2(const float* __restrict__ wf2) {
    int t = threadIdx.x;
    const float4* wr = (const float4*)&wf2[(size_t)blockIdx.x * 512];
    const float4* gr = (const float4*)d_f1;
    float a = 0.f;
    if (t < 128) {
        float4 wv = __ldg(&wr[t]); float4 gv = gr[t];
        a = wv.x * gv.x + wv.y * gv.y + wv.z * gv.z + wv.w * gv.w;
    }
    float r = blk_dot_reduce(a);
    if (t == 0) d_f2[blockIdx.x] = fmaxf(r, 0.0f);
}

__global__ void __launch_bounds__(128) k_head3(const float* __restrict__ wf3,
                                               float* __restrict__ out) {
    int t = threadIdx.x;
    const float4* wr = (const float4*)&wf3[(size_t)blockIdx.x * 256];
    const float4* gr = (const float4*)d_f2;
    float a = 0.f;
    if (t < 64) {
        float4 wv = __ldg(&wr[t]); float4 gv = gr[t];
        a = wv.x * gv.x + wv.y * gv.y + wv.z * gv.z + wv.w * gv.w;
    }
    float r = blk_dot_reduce(a);
    if (t == 0) out[blockIdx.x] = r;
}

// ---------------- launch ----------------
extern "C" void kernel_launch(void* const* d_in, const int* in_sizes, int n_in,
                              void* d_out, int out_size) {
    const float* x       = (const float*)d_in[0];
    const int*   indices = (const int*)d_in[2];   // indptr (d_in[1]) fixed K=16
    const float* w1  = (const float*)d_in[3];
    const float* w2  = (const float*)d_in[4];
    const float* w3  = (const float*)d_in[5];
    const float* w4  = (const float*)d_in[6];
    const float* w5  = (const float*)d_in[7];
    const float* wf1 = (const float*)d_in[8];
    const float* wf2 = (const float*)d_in[9];
    const float* wf3 = (const float*)d_in[10];
    float* out = (float*)d_out;

    const int SMEM_F = 35840 * 2 + 576 * 4;           // 74,176 B
    const int SMEM_5 = (51200 + 2 * 25600) * 2;       // 204,800 B
    cudaFuncSetAttribute(k_mlp1234, cudaFuncAttributeMaxDynamicSharedMemorySize, SMEM_F);
    cudaFuncSetAttribute(k_mlp5max, cudaFuncAttributeMaxDynamicSharedMemorySize, SMEM_5);

    k_prep_w <<<64,  256>>>(w2, w3, w4);
    k_prep_w5<<<768, 256>>>(w5);
    k_mlp1234<<<NPTS / 128, 256, SMEM_F>>>(x, w1);
    k_gmax   <<<NPTS / 8,   256>>>(indices);
    k_mlp5max<<<NPTS / 256, 512, SMEM_5>>>();
    k_greduce<<<32, 256>>>();
    k_head1  <<<512, 128>>>(wf1);
    k_head2  <<<256, 128>>>(wf2);
    k_head3  <<<40,  128>>>(wf3, out);
}

// round 6
// speedup vs baseline: 14.7184x; 1.0002x over previous
#include <cuda_runtime.h>
#include <cuda_fp16.h>
#include <cstdint>

#define NPTS 262144

// ---------------- device scratch (no allocations allowed) ----------------
__device__ __half d_h2h [NPTS * 64];      // after mlp1+mlp2 (relu, fp16)
__device__ __half d_xgmh[NPTS * 64];      // neighbor max-pooled (fp16)
__device__ __half d_h4h [NPTS * 128];     // after mlp3+mlp4 (relu, fp16)
__device__ __half d_w2h [64 * 64];
__device__ __half d_w3h [64 * 64];
__device__ __half d_w4h [128 * 64];
__device__ __half d_w5h [1024 * 192];
__device__ float  d_partial[1024 * 1024]; // per-rowtile per-col max (pre-relu)
__device__ float  d_g  [1024];
__device__ float  d_f1 [512];
__device__ float  d_f2 [256];

// ---------------- helpers ----------------
__device__ __forceinline__ uint32_t smem_u32(const void* p) {
    uint32_t a;
    asm("{ .reg .u64 t; cvta.to.shared.u64 t, %1; cvt.u32.u64 %0, t; }"
        : "=r"(a) : "l"(p));
    return a;
}
__device__ __forceinline__ void cp16(uint32_t dst, const void* src) {
    asm volatile("cp.async.cg.shared.global [%0], [%1], 16;"
                 :: "r"(dst), "l"(src) : "memory");
}
#define CP_COMMIT() asm volatile("cp.async.commit_group;" ::: "memory")
#define CP_WAIT0()  asm volatile("cp.async.wait_group 0;" ::: "memory")
#define CP_WAIT1()  asm volatile("cp.async.wait_group 1;" ::: "memory")

__device__ __forceinline__ void ldsm4(uint32_t& r0, uint32_t& r1,
                                      uint32_t& r2, uint32_t& r3, uint32_t addr) {
    asm volatile("ldmatrix.sync.aligned.m8n8.x4.shared.b16 {%0,%1,%2,%3}, [%4];"
                 : "=r"(r0), "=r"(r1), "=r"(r2), "=r"(r3) : "r"(addr));
}
__device__ __forceinline__ void mma_f16(float* c, uint32_t a0, uint32_t a1,
                                        uint32_t a2, uint32_t a3,
                                        uint32_t b0, uint32_t b1) {
    asm volatile(
        "mma.sync.aligned.m16n8k16.row.col.f32.f16.f16.f32 "
        "{%0,%1,%2,%3}, {%4,%5,%6,%7}, {%8,%9}, {%0,%1,%2,%3};"
        : "+f"(c[0]), "+f"(c[1]), "+f"(c[2]), "+f"(c[3])
        : "r"(a0), "r"(a1), "r"(a2), "r"(a3), "r"(b0), "r"(b1));
}
__device__ __forceinline__ uint32_t ph2_relu(float x, float y) {
    __half2 h = __floats2half2_rn(fmaxf(x, 0.f), fmaxf(y, 0.f));
    return *reinterpret_cast<uint32_t*>(&h);
}

// B stationed in smem rows [n x 72-stride]; GEMM over K=64, N=64
__device__ __forceinline__ void gemm64(uint32_t sbase, const uint32_t (&a)[4][4],
                                       float (&c)[8][4], int lane) {
#pragma unroll
    for (int j = 0; j < 8; j++)
#pragma unroll
        for (int r = 0; r < 4; r++) c[j][r] = 0.f;
#pragma unroll
    for (int q = 0; q < 4; q++) {
#pragma unroll
        for (int jp = 0; jp < 4; jp++) {
            uint32_t B0, B1, B2, B3;
            uint32_t bn = 16 * jp + (lane & 7) + 8 * (lane >> 4);
            uint32_t bk = q * 16 + 8 * ((lane >> 3) & 1);
            ldsm4(B0, B1, B2, B3, sbase + (bn * 72 + bk) * 2);
            mma_f16(c[2 * jp],     a[q][0], a[q][1], a[q][2], a[q][3], B0, B1);
            mma_f16(c[2 * jp + 1], a[q][0], a[q][1], a[q][2], a[q][3], B2, B3);
        }
    }
}
__device__ __forceinline__ void pack_relu(const float (&c)[8][4], uint32_t (&a)[4][4]) {
#pragma unroll
    for (int q = 0; q < 4; q++) {
        a[q][0] = ph2_relu(c[2 * q][0],     c[2 * q][1]);
        a[q][1] = ph2_relu(c[2 * q][2],     c[2 * q][3]);
        a[q][2] = ph2_relu(c[2 * q + 1][0], c[2 * q + 1][1]);
        a[q][3] = ph2_relu(c[2 * q + 1][2], c[2 * q + 1][3]);
    }
}

// ---------------- weight prep: fp32 -> fp16 (w2, w3, w4) ----------------
__global__ void __launch_bounds__(256) k_prep_w(const float* __restrict__ w2,
                                                const float* __restrict__ w3,
                                                const float* __restrict__ w4) {
    int i = blockIdx.x * 256 + threadIdx.x;   // 16384 total
    if (i < 4096)       d_w2h[i]        = __float2half_rn(w2[i]);
    else if (i < 8192)  d_w3h[i - 4096] = __float2half_rn(w3[i - 4096]);
    else                d_w4h[i - 8192] = __float2half_rn(w4[i - 8192]);
}
__global__ void __launch_bounds__(256) k_prep_w5(const float* __restrict__ w5) {
    int i = blockIdx.x * 256 + threadIdx.x;   // 196608 total
    d_w5h[i] = __float2half_rn(w5[i]);
}

// ---------------- fused mlp1..mlp4 : x[N,3] -> h2[N,64], h4[N,128] ----------------
// Block: 128 points, 8 warps x 16 rows. mlp1 computed scalar-fp32 directly into
// A-fragment layout; GEMM2/3/4 chained in registers (c-frag -> a-frag repack).
__global__ void __launch_bounds__(256, 2) k_mlp1234(const float* __restrict__ x,
                                                    const float* __restrict__ w1) {
    extern __shared__ __half sh[];
    const int OFF_W2 = 0, OFF_W3 = 4608, OFF_W4 = 9216, OFF_OUT = 18432;
    __half* s_out = sh + OFF_OUT;                   // 128*136
    float*  s_xf  = (float*)(sh + 35840);           // 128*3
    float*  s_w1f = s_xf + 384;                     // 64*3

    int t = threadIdx.x, lane = t & 31, w = t >> 5;
    int g = lane >> 2, tig = lane & 3;
    size_t p0 = (size_t)blockIdx.x * 128;
    uint32_t sb = smem_u32(sh);

    // stage weights (fp16, stride 72) via cp.async
    for (int i = t; i < 512; i += 256) {
        int r = i >> 3, c = i & 7;
        cp16(sb + (uint32_t)(OFF_W2 + r * 72 + c * 8) * 2, d_w2h + r * 64 + c * 8);
        cp16(sb + (uint32_t)(OFF_W3 + r * 72 + c * 8) * 2, d_w3h + r * 64 + c * 8);
    }
    for (int i = t; i < 1024; i += 256) {
        int r = i >> 3, c = i & 7;
        cp16(sb + (uint32_t)(OFF_W4 + r * 72 + c * 8) * 2, d_w4h + r * 64 + c * 8);
    }
    // x tile + w1 (fp32)
    for (int i = t; i < 384; i += 256) s_xf[i] = x[p0 * 3 + i];
    if (t < 192) s_w1f[t] = w1[t];
    CP_COMMIT(); CP_WAIT0();
    __syncthreads();

    // mlp1: compute this thread's 32 h1 values straight into a-frag layout
    int r0 = 16 * w + g;
    float xa0 = s_xf[r0 * 3], xa1 = s_xf[r0 * 3 + 1], xa2 = s_xf[r0 * 3 + 2];
    float xb0 = s_xf[(r0 + 8) * 3], xb1 = s_xf[(r0 + 8) * 3 + 1], xb2 = s_xf[(r0 + 8) * 3 + 2];
    uint32_t a1h[4][4];
#pragma unroll
    for (int q = 0; q < 4; q++) {
        int f0 = 16 * q + 2 * tig;
        int f2 = f0 + 8;
#define DOT3(f, u0, u1, u2) \
        fmaf(s_w1f[(f)*3+2], u2, fmaf(s_w1f[(f)*3+1], u1, s_w1f[(f)*3] * u0))
        a1h[q][0] = ph2_relu(DOT3(f0, xa0, xa1, xa2), DOT3(f0 + 1, xa0, xa1, xa2));
        a1h[q][1] = ph2_relu(DOT3(f0, xb0, xb1, xb2), DOT3(f0 + 1, xb0, xb1, xb2));
        a1h[q][2] = ph2_relu(DOT3(f2, xa0, xa1, xa2), DOT3(f2 + 1, xa0, xa1, xa2));
        a1h[q][3] = ph2_relu(DOT3(f2, xb0, xb1, xb2), DOT3(f2 + 1, xb0, xb1, xb2));
#undef DOT3
    }

    // GEMM2: h2 = relu(h1 @ w2^T)
    float c2[8][4];
    uint32_t a2h[4][4];
    gemm64(sb + OFF_W2 * 2, a1h, c2, lane);
    pack_relu(c2, a2h);

    // stage h2 -> s_out, then coalesced global store
#pragma unroll
    for (int q = 0; q < 4; q++) {
        int c0 = 16 * q + 2 * tig, cc2 = c0 + 8;
        *(uint32_t*)&s_out[r0 * 136 + c0]        = a2h[q][0];
        *(uint32_t*)&s_out[(r0 + 8) * 136 + c0]  = a2h[q][1];
        *(uint32_t*)&s_out[r0 * 136 + cc2]       = a2h[q][2];
        *(uint32_t*)&s_out[(r0 + 8) * 136 + cc2] = a2h[q][3];
    }
    __syncthreads();
    for (int i = t; i < 1024; i += 256) {
        int r = i >> 3, c = i & 7;
        *(uint4*)&d_h2h[(p0 + r) * 64 + c * 8] = *(uint4*)&s_out[r * 136 + c * 8];
    }
    __syncthreads();   // s_out reused for h4

    // GEMM3: h3 = relu(h2 @ w3^T)
    float c3[8][4];
    uint32_t a3h[4][4];
    gemm64(sb + OFF_W3 * 2, a2h, c3, lane);
    pack_relu(c3, a3h);

    // GEMM4: h4 = relu(h3 @ w4^T), N=128 in two halves
#pragma unroll
    for (int nh = 0; nh < 2; nh++) {
        float c4[8][4];
#pragma unroll
        for (int j = 0; j < 8; j++)
#pragma unroll
            for (int r = 0; r < 4; r++) c4[j][r] = 0.f;
#pragma unroll
        for (int q = 0; q < 4; q++) {
#pragma unroll
            for (int jp = 0; jp < 4; jp++) {
                uint32_t B0, B1, B2, B3;
                uint32_t bn = 64 * nh + 16 * jp + (lane & 7) + 8 * (lane >> 4);
                uint32_t bk = q * 16 + 8 * ((lane >> 3) & 1);
                ldsm4(B0, B1, B2, B3, sb + (OFF_W4 + bn * 72 + bk) * 2);
                mma_f16(c4[2 * jp],     a3h[q][0], a3h[q][1], a3h[q][2], a3h[q][3], B0, B1);
                mma_f16(c4[2 * jp + 1], a3h[q][0], a3h[q][1], a3h[q][2], a3h[q][3], B2, B3);
            }
        }
#pragma unroll
        for (int j2 = 0; j2 < 8; j2++) {
            int coln = 64 * nh + 8 * j2 + 2 * tig;
            *(uint32_t*)&s_out[r0 * 136 + coln]       = ph2_relu(c4[j2][0], c4[j2][1]);
            *(uint32_t*)&s_out[(r0 + 8) * 136 + coln] = ph2_relu(c4[j2][2], c4[j2][3]);
        }
    }
    __syncthreads();
    for (int i = t; i < 2048; i += 256) {
        int r = i >> 4, c = i & 15;
        *(uint4*)&d_h4h[(p0 + r) * 128 + c * 8] = *(uint4*)&s_out[r * 136 + c * 8];
    }
}

// ---------------- graph max pooling (K=16), fp16, 32 threads/point ----------------
__global__ void __launch_bounds__(256) k_gmax(const int* __restrict__ indices) {
    __shared__ int s_idx[8][16];
    int t = threadIdx.x, lane = t & 31, pl = t >> 5;
    int base = blockIdx.x * 8;
    if (t < 128) s_idx[t >> 4][t & 15] = indices[base * 16 + t];
    __syncthreads();

    __half2 m = __float2half2_rn(0.0f);   // h2 >= 0
    const __half2* h2 = (const __half2*)d_h2h;
#pragma unroll
    for (int j = 0; j < 16; j++) {
        unsigned off = (unsigned)s_idx[pl][j] * 32u + (unsigned)lane;  // 32-bit addr math
        m = __hmax2(m, h2[off]);
    }
    ((__half2*)d_xgmh)[(unsigned)(base + pl) * 32u + lane] = m;
}

// ---------------- mlp5 + global max : 256-row blocks, double-buffered B ----------------
__global__ void __launch_bounds__(512) k_mlp5max() {
    extern __shared__ __half sh5[];
    __half* s_a = sh5;                        // 256*200
    __shared__ float s_red[16][32];

    int t = threadIdx.x, lane = t & 31, w = t >> 5;
    int wm = w >> 2, wn = w & 3;
    size_t m0 = (size_t)blockIdx.x * 256;
    uint32_t ab = smem_u32(s_a);
    uint32_t bb0 = ab + 51200 * 2, bb1 = ab + 76800 * 2;

    // stage A (once): 256 rows x 24 16B-chunks
    for (int i = t; i < 6144; i += 512) {
        int r = i / 24, c = i % 24;
        const __half* src = (c < 8) ? d_xgmh + (m0 + r) * 64 + c * 8
                                    : d_h4h + (m0 + r) * 128 + (c - 8) * 8;
        cp16(ab + (uint32_t)(r * 200 + c * 8) * 2, src);
    }
    for (int i = t; i < 3072; i += 512) {
        int r = i / 24, c = i % 24;
        cp16(bb0 + (uint32_t)(r * 200 + c * 8) * 2, d_w5h + (size_t)r * 192 + c * 8);
    }
    CP_COMMIT();
    for (int i = t; i < 3072; i += 512) {
        int r = i / 24, c = i % 24;
        cp16(bb1 + (uint32_t)(r * 200 + c * 8) * 2, d_w5h + (size_t)(128 + r) * 192 + c * 8);
    }
    CP_COMMIT();

    for (int nt = 0; nt < 8; nt++) {
        CP_WAIT1();          // current buffer's group done (<=1 pending)
        __syncthreads();
        uint32_t cur = (nt & 1) ? bb1 : bb0;

        float c_[4][4][4];
#pragma unroll
        for (int i = 0; i < 4; i++)
#pragma unroll
            for (int j = 0; j < 4; j++)
#pragma unroll
                for (int r = 0; r < 4; r++) c_[i][j][r] = 0.f;

#pragma unroll
        for (int q = 0; q < 12; q++) {
            uint32_t a_[4][4], b_[2][4];
#pragma unroll
            for (int mt = 0; mt < 4; mt++) {
                uint32_t row = 64 * wm + 16 * mt + (lane & 15);
                uint32_t kh  = q * 16 + 8 * (lane >> 4);
                ldsm4(a_[mt][0], a_[mt][1], a_[mt][2], a_[mt][3],
                      ab + (row * 200 + kh) * 2);
            }
#pragma unroll
            for (int p = 0; p < 2; p++) {
                uint32_t bn = 32 * wn + 16 * p + (lane & 7) + 8 * (lane >> 4);
                uint32_t kh = q * 16 + 8 * ((lane >> 3) & 1);
                ldsm4(b_[p][0], b_[p][1], b_[p][2], b_[p][3],
                      cur + (bn * 200 + kh) * 2);
            }
#pragma unroll
            for (int mt = 0; mt < 4; mt++) {
                mma_f16(c_[mt][0], a_[mt][0], a_[mt][1], a_[mt][2], a_[mt][3], b_[0][0], b_[0][1]);
                mma_f16(c_[mt][1], a_[mt][0], a_[mt][1], a_[mt][2], a_[mt][3], b_[0][2], b_[0][3]);
                mma_f16(c_[mt][2], a_[mt][0], a_[mt][1], a_[mt][2], a_[mt][3], b_[1][0], b_[1][1]);
                mma_f16(c_[mt][3], a_[mt][0], a_[mt][1], a_[mt][2], a_[mt][3], b_[1][2], b_[1][3]);
            }
        }
        __syncthreads();     // all warps done reading cur

        if (nt < 6) {        // prefetch nt+2 into the buffer just freed
            uint32_t nxt = (nt & 1) ? bb1 : bb0;
            for (int i = t; i < 3072; i += 512) {
                int r = i / 24, c = i % 24;
                cp16(nxt + (uint32_t)(r * 200 + c * 8) * 2,
                     d_w5h + (size_t)((nt + 2) * 128 + r) * 192 + c * 8);
            }
            CP_COMMIT();
        }

        // epilogue: col-max over this warp's 64 rows, then block-wide over 256
        float cm[8];
#pragma unroll
        for (int nq = 0; nq < 4; nq++) {
            float v0 = fmaxf(fmaxf(c_[0][nq][0], c_[0][nq][2]),
                             fmaxf(c_[1][nq][0], c_[1][nq][2]));
            v0 = fmaxf(v0, fmaxf(fmaxf(c_[2][nq][0], c_[2][nq][2]),
                                 fmaxf(c_[3][nq][0], c_[3][nq][2])));
            float v1 = fmaxf(fmaxf(c_[0][nq][1], c_[0][nq][3]),
                             fmaxf(c_[1][nq][1], c_[1][nq][3]));
            v1 = fmaxf(v1, fmaxf(fmaxf(c_[2][nq][1], c_[2][nq][3]),
                                 fmaxf(c_[3][nq][1], c_[3][nq][3])));
            cm[nq * 2 + 0] = v0;
            cm[nq * 2 + 1] = v1;
        }
#pragma unroll
        for (int off = 4; off < 32; off <<= 1)
#pragma unroll
            for (int j = 0; j < 8; j++)
                cm[j] = fmaxf(cm[j], __shfl_xor_sync(0xffffffffu, cm[j], off));
        if (lane < 4) {
#pragma unroll
            for (int nq = 0; nq < 4; nq++) {
                s_red[w][nq * 8 + lane * 2 + 0] = cm[nq * 2 + 0];
                s_red[w][nq * 8 + lane * 2 + 1] = cm[nq * 2 + 1];
            }
        }
        __syncthreads();
        if (t < 128) {
            int grp = t >> 5, c = t & 31;
            float v = fmaxf(fmaxf(s_red[grp][c], s_red[4 + grp][c]),
                            fmaxf(s_red[8 + grp][c], s_red[12 + grp][c]));
            d_partial[(size_t)blockIdx.x * 1024 + nt * 128 + t] = v;
        }
    }
}

// ---------------- global reduce: d_partial[1024,1024] -> d_g[1024] (relu) ----------------
__global__ void __launch_bounds__(256) k_greduce() {
    __shared__ float sr[8][32];
    int c  = blockIdx.x * 32 + (threadIdx.x & 31);
    int rg = threadIdx.x >> 5;
    float m = -1e30f;
#pragma unroll 4
    for (int b = rg * 128; b < rg * 128 + 128; b++)
        m = fmaxf(m, d_partial[(size_t)b * 1024 + c]);
    sr[rg][threadIdx.x & 31] = m;
    __syncthreads();
    if (threadIdx.x < 32) {
        float v = sr[0][threadIdx.x];
#pragma unroll
        for (int r = 1; r < 8; r++) v = fmaxf(v, sr[r][threadIdx.x]);
        d_g[blockIdx.x * 32 + threadIdx.x] = fmaxf(v, 0.0f);
    }
}

// ---------------- head: 3 small GEMVs ----------------
__device__ __forceinline__ float blk_dot_reduce(float a) {
#pragma unroll
    for (int o = 16; o; o >>= 1) a += __shfl_xor_sync(0xffffffffu, a, o);
    __shared__ float s[4];
    int t = threadIdx.x;
    if ((t & 31) == 0) s[t >> 5] = a;
    __syncthreads();
    return s[0] + s[1] + s[2] + s[3];
}

__global__ void __launch_bounds__(128) k_head1(const float* __restrict__ wf1) {
    int t = threadIdx.x;
    const float4* wr = (const float4*)&wf1[(size_t)blockIdx.x * 1024];
    const float4* gr = (const float4*)d_g;
    float a = 0.f;
    for (int k = t; k < 256; k += 128) {
        float4 wv = __ldg(&wr[k]); float4 gv = gr[k];
        a += wv.x * gv.x + wv.y * gv.y + wv.z * gv.z + wv.w * gv.w;
    }
    float r = blk_dot_reduce(a);
    if (t == 0) d_f1[blockIdx.x] = fmaxf(r, 0.0f);
}

__global__ void __launch_bounds__(128) k_head2(const float* __restrict__ wf2) {
    int t = threadIdx.x;
    const float4* wr = (const float4*)&wf2[(size_t)blockIdx.x * 512];
    const float4* gr = (const float4*)d_f1;
    float a = 0.f;
    if (t < 128) {
        float4 wv = __ldg(&wr[t]); float4 gv = gr[t];
        a = wv.x * gv.x + wv.y * gv.y + wv.z * gv.z + wv.w * gv.w;
    }
    float r = blk_dot_reduce(a);
    if (t == 0) d_f2[blockIdx.x] = fmaxf(r, 0.0f);
}

__global__ void __launch_bounds__(128) k_head3(const float* __restrict__ wf3,
                                               float* __restrict__ out) {
    int t = threadIdx.x;
    const float4* wr = (const float4*)&wf3[(size_t)blockIdx.x * 256];
    const float4* gr = (const float4*)d_f2;
    float a = 0.f;
    if (t < 64) {
        float4 wv = __ldg(&wr[t]); float4 gv = gr[t];
        a = wv.x * gv.x + wv.y * gv.y + wv.z * gv.z + wv.w * gv.w;
    }
    float r = blk_dot_reduce(a);
    if (t == 0) out[blockIdx.x] = r;
}

// ---------------- launch ----------------
extern "C" void kernel_launch(void* const* d_in, const int* in_sizes, int n_in,
                              void* d_out, int out_size) {
    const float* x       = (const float*)d_in[0];
    const int*   indices = (const int*)d_in[2];   // indptr (d_in[1]) fixed K=16
    const float* w1  = (const float*)d_in[3];
    const float* w2  = (const float*)d_in[4];
    const float* w3  = (const float*)d_in[5];
    const float* w4  = (const float*)d_in[6];
    const float* w5  = (const float*)d_in[7];
    const float* wf1 = (const float*)d_in[8];
    const float* wf2 = (const float*)d_in[9];
    const float* wf3 = (const float*)d_in[10];
    float* out = (float*)d_out;

    const int SMEM_F = 35840 * 2 + 576 * 4;           // 74,176 B
    const int SMEM_5 = (51200 + 2 * 25600) * 2;       // 204,800 B
    cudaFuncSetAttribute(k_mlp1234, cudaFuncAttributeMaxDynamicSharedMemorySize, SMEM_F);
    cudaFuncSetAttribute(k_mlp5max, cudaFuncAttributeMaxDynamicSharedMemorySize, SMEM_5);

    k_prep_w <<<64,  256>>>(w2, w3, w4);
    k_prep_w5<<<768, 256>>>(w5);
    k_mlp1234<<<NPTS / 128, 256, SMEM_F>>>(x, w1);
    k_gmax   <<<NPTS / 8,   256>>>(indices);
    k_mlp5max<<<NPTS / 256, 512, SMEM_5>>>();
    k_greduce<<<32, 256>>>();
    k_head1  <<<512, 128>>>(wf1);
    k_head2  <<<256, 128>>>(wf2);
    k_head3  <<<40,  128>>>(wf3, out);
}

// round 7
// speedup vs baseline: 15.0237x; 1.0207x over previous
#include <cuda_runtime.h>
#include <cuda_fp16.h>
#include <cstdint>

#define NPTS 262144

// ---------------- device scratch (no allocations allowed) ----------------
__device__ __half d_h2h [NPTS * 64];      // after mlp1+mlp2 (relu, fp16)
__device__ __half d_xgmh[NPTS * 64];      // neighbor max-pooled (fp16)
__device__ __half d_h4h [NPTS * 128];     // after mlp3+mlp4 (relu, fp16)
__device__ __half d_w2h [64 * 64];
__device__ __half d_w3h [64 * 64];
__device__ __half d_w4h [128 * 64];
__device__ __half d_w5h [1024 * 192];
__device__ float  d_g  [1024];            // global max (post-relu), atomicMax target
__device__ float  d_f1 [512];
__device__ float  d_f2 [256];

// ---------------- helpers ----------------
__device__ __forceinline__ uint32_t smem_u32(const void* p) {
    uint32_t a;
    asm("{ .reg .u64 t; cvta.to.shared.u64 t, %1; cvt.u32.u64 %0, t; }"
        : "=r"(a) : "l"(p));
    return a;
}
__device__ __forceinline__ void cp16(uint32_t dst, const void* src) {
    asm volatile("cp.async.cg.shared.global [%0], [%1], 16;"
                 :: "r"(dst), "l"(src) : "memory");
}
#define CP_COMMIT() asm volatile("cp.async.commit_group;" ::: "memory")
#define CP_WAIT0()  asm volatile("cp.async.wait_group 0;" ::: "memory")
#define CP_WAIT1()  asm volatile("cp.async.wait_group 1;" ::: "memory")

__device__ __forceinline__ void ldsm4(uint32_t& r0, uint32_t& r1,
                                      uint32_t& r2, uint32_t& r3, uint32_t addr) {
    asm volatile("ldmatrix.sync.aligned.m8n8.x4.shared.b16 {%0,%1,%2,%3}, [%4];"
                 : "=r"(r0), "=r"(r1), "=r"(r2), "=r"(r3) : "r"(addr));
}
__device__ __forceinline__ void mma_f16(float* c, uint32_t a0, uint32_t a1,
                                        uint32_t a2, uint32_t a3,
                                        uint32_t b0, uint32_t b1) {
    asm volatile(
        "mma.sync.aligned.m16n8k16.row.col.f32.f16.f16.f32 "
        "{%0,%1,%2,%3}, {%4,%5,%6,%7}, {%8,%9}, {%0,%1,%2,%3};"
        : "+f"(c[0]), "+f"(c[1]), "+f"(c[2]), "+f"(c[3])
        : "r"(a0), "r"(a1), "r"(a2), "r"(a3), "r"(b0), "r"(b1));
}
__device__ __forceinline__ uint32_t ph2_relu(float x, float y) {
    __half2 h = __floats2half2_rn(fmaxf(x, 0.f), fmaxf(y, 0.f));
    return *reinterpret_cast<uint32_t*>(&h);
}

// B stationed in smem rows [n x 72-stride]; GEMM over K=64, N=64
__device__ __forceinline__ void gemm64(uint32_t sbase, const uint32_t (&a)[4][4],
                                       float (&c)[8][4], int lane) {
#pragma unroll
    for (int j = 0; j < 8; j++)
#pragma unroll
        for (int r = 0; r < 4; r++) c[j][r] = 0.f;
#pragma unroll
    for (int q = 0; q < 4; q++) {
#pragma unroll
        for (int jp = 0; jp < 4; jp++) {
            uint32_t B0, B1, B2, B3;
            uint32_t bn = 16 * jp + (lane & 7) + 8 * (lane >> 4);
            uint32_t bk = q * 16 + 8 * ((lane >> 3) & 1);
            ldsm4(B0, B1, B2, B3, sbase + (bn * 72 + bk) * 2);
            mma_f16(c[2 * jp],     a[q][0], a[q][1], a[q][2], a[q][3], B0, B1);
            mma_f16(c[2 * jp + 1], a[q][0], a[q][1], a[q][2], a[q][3], B2, B3);
        }
    }
}
__device__ __forceinline__ void pack_relu(const float (&c)[8][4], uint32_t (&a)[4][4]) {
#pragma unroll
    for (int q = 0; q < 4; q++) {
        a[q][0] = ph2_relu(c[2 * q][0],     c[2 * q][1]);
        a[q][1] = ph2_relu(c[2 * q][2],     c[2 * q][3]);
        a[q][2] = ph2_relu(c[2 * q + 1][0], c[2 * q + 1][1]);
        a[q][3] = ph2_relu(c[2 * q + 1][2], c[2 * q + 1][3]);
    }
}

// ---------------- prep: w2..w5 fp32->fp16 + zero d_g (one kernel) ----------------
__global__ void __launch_bounds__(256) k_prep(const float* __restrict__ w2,
                                              const float* __restrict__ w3,
                                              const float* __restrict__ w4,
                                              const float* __restrict__ w5) {
    int b = blockIdx.x, t = threadIdx.x;
    if (b < 768) {
        int i = b * 256 + t;                       // 196608 w5 elements
        d_w5h[i] = __float2half_rn(w5[i]);
    } else if (b < 832) {
        int i = (b - 768) * 256 + t;               // 16384 w2/w3/w4 elements
        if (i < 4096)      d_w2h[i]        = __float2half_rn(w2[i]);
        else if (i < 8192) d_w3h[i - 4096] = __float2half_rn(w3[i - 4096]);
        else               d_w4h[i - 8192] = __float2half_rn(w4[i - 8192]);
    } else {
        d_g[(b - 832) * 256 + t] = 0.0f;           // 1024 (relu output >= 0)
    }
}

// ---------------- fused mlp1..mlp4 : x[N,3] -> h2[N,64], h4[N,128] ----------------
__global__ void __launch_bounds__(256, 2) k_mlp1234(const float* __restrict__ x,
                                                    const float* __restrict__ w1) {
    extern __shared__ __half sh[];
    const int OFF_W2 = 0, OFF_W3 = 4608, OFF_W4 = 9216, OFF_OUT = 18432;
    __half* s_out = sh + OFF_OUT;                   // 128*136
    float*  s_xf  = (float*)(sh + 35840);           // 128*3
    float*  s_w1f = s_xf + 384;                     // 64*3

    int t = threadIdx.x, lane = t & 31, w = t >> 5;
    int g = lane >> 2, tig = lane & 3;
    size_t p0 = (size_t)blockIdx.x * 128;
    uint32_t sb = smem_u32(sh);

    for (int i = t; i < 512; i += 256) {
        int r = i >> 3, c = i & 7;
        cp16(sb + (uint32_t)(OFF_W2 + r * 72 + c * 8) * 2, d_w2h + r * 64 + c * 8);
        cp16(sb + (uint32_t)(OFF_W3 + r * 72 + c * 8) * 2, d_w3h + r * 64 + c * 8);
    }
    for (int i = t; i < 1024; i += 256) {
        int r = i >> 3, c = i & 7;
        cp16(sb + (uint32_t)(OFF_W4 + r * 72 + c * 8) * 2, d_w4h + r * 64 + c * 8);
    }
    for (int i = t; i < 384; i += 256) s_xf[i] = x[p0 * 3 + i];
    if (t < 192) s_w1f[t] = w1[t];
    CP_COMMIT(); CP_WAIT0();
    __syncthreads();

    // mlp1: this thread's 32 h1 values straight into a-frag layout
    int r0 = 16 * w + g;
    float xa0 = s_xf[r0 * 3], xa1 = s_xf[r0 * 3 + 1], xa2 = s_xf[r0 * 3 + 2];
    float xb0 = s_xf[(r0 + 8) * 3], xb1 = s_xf[(r0 + 8) * 3 + 1], xb2 = s_xf[(r0 + 8) * 3 + 2];
    uint32_t a1h[4][4];
#pragma unroll
    for (int q = 0; q < 4; q++) {
        int f0 = 16 * q + 2 * tig;
        int f2 = f0 + 8;
#define DOT3(f, u0, u1, u2) \
        fmaf(s_w1f[(f)*3+2], u2, fmaf(s_w1f[(f)*3+1], u1, s_w1f[(f)*3] * u0))
        a1h[q][0] = ph2_relu(DOT3(f0, xa0, xa1, xa2), DOT3(f0 + 1, xa0, xa1, xa2));
        a1h[q][1] = ph2_relu(DOT3(f0, xb0, xb1, xb2), DOT3(f0 + 1, xb0, xb1, xb2));
        a1h[q][2] = ph2_relu(DOT3(f2, xa0, xa1, xa2), DOT3(f2 + 1, xa0, xa1, xa2));
        a1h[q][3] = ph2_relu(DOT3(f2, xb0, xb1, xb2), DOT3(f2 + 1, xb0, xb1, xb2));
#undef DOT3
    }

    // GEMM2: h2 = relu(h1 @ w2^T)
    float c2[8][4];
    uint32_t a2h[4][4];
    gemm64(sb + OFF_W2 * 2, a1h, c2, lane);
    pack_relu(c2, a2h);

#pragma unroll
    for (int q = 0; q < 4; q++) {
        int c0 = 16 * q + 2 * tig, cc2 = c0 + 8;
        *(uint32_t*)&s_out[r0 * 136 + c0]        = a2h[q][0];
        *(uint32_t*)&s_out[(r0 + 8) * 136 + c0]  = a2h[q][1];
        *(uint32_t*)&s_out[r0 * 136 + cc2]       = a2h[q][2];
        *(uint32_t*)&s_out[(r0 + 8) * 136 + cc2] = a2h[q][3];
    }
    __syncthreads();
    for (int i = t; i < 1024; i += 256) {
        int r = i >> 3, c = i & 7;
        *(uint4*)&d_h2h[(p0 + r) * 64 + c * 8] = *(uint4*)&s_out[r * 136 + c * 8];
    }
    __syncthreads();   // s_out reused for h4

    // GEMM3: h3 = relu(h2 @ w3^T)
    float c3[8][4];
    uint32_t a3h[4][4];
    gemm64(sb + OFF_W3 * 2, a2h, c3, lane);
    pack_relu(c3, a3h);

    // GEMM4: h4 = relu(h3 @ w4^T), N=128 in two halves
#pragma unroll
    for (int nh = 0; nh < 2; nh++) {
        float c4[8][4];
#pragma unroll
        for (int j = 0; j < 8; j++)
#pragma unroll
            for (int r = 0; r < 4; r++) c4[j][r] = 0.f;
#pragma unroll
        for (int q = 0; q < 4; q++) {
#pragma unroll
            for (int jp = 0; jp < 4; jp++) {
                uint32_t B0, B1, B2, B3;
                uint32_t bn = 64 * nh + 16 * jp + (lane & 7) + 8 * (lane >> 4);
                uint32_t bk = q * 16 + 8 * ((lane >> 3) & 1);
                ldsm4(B0, B1, B2, B3, sb + (OFF_W4 + bn * 72 + bk) * 2);
                mma_f16(c4[2 * jp],     a3h[q][0], a3h[q][1], a3h[q][2], a3h[q][3], B0, B1);
                mma_f16(c4[2 * jp + 1], a3h[q][0], a3h[q][1], a3h[q][2], a3h[q][3], B2, B3);
            }
        }
#pragma unroll
        for (int j2 = 0; j2 < 8; j2++) {
            int coln = 64 * nh + 8 * j2 + 2 * tig;
            *(uint32_t*)&s_out[r0 * 136 + coln]       = ph2_relu(c4[j2][0], c4[j2][1]);
            *(uint32_t*)&s_out[(r0 + 8) * 136 + coln] = ph2_relu(c4[j2][2], c4[j2][3]);
        }
    }
    __syncthreads();
    for (int i = t; i < 2048; i += 256) {
        int r = i >> 4, c = i & 15;
        *(uint4*)&d_h4h[(p0 + r) * 128 + c * 8] = *(uint4*)&s_out[r * 136 + c * 8];
    }
}

// ---------------- graph max pooling (K=16), fp16, 32 threads/point ----------------
__global__ void __launch_bounds__(256) k_gmax(const int* __restrict__ indices) {
    __shared__ int s_idx[8][16];
    int t = threadIdx.x, lane = t & 31, pl = t >> 5;
    int base = blockIdx.x * 8;
    if (t < 128) s_idx[t >> 4][t & 15] = indices[base * 16 + t];
    __syncthreads();

    __half2 m = __float2half2_rn(0.0f);   // h2 >= 0
    const __half2* h2 = (const __half2*)d_h2h;
#pragma unroll
    for (int j = 0; j < 16; j++) {
        unsigned off = (unsigned)s_idx[pl][j] * 32u + (unsigned)lane;
        m = __hmax2(m, h2[off]);
    }
    ((__half2*)d_xgmh)[(unsigned)(base + pl) * 32u + lane] = m;
}

// ---------------- mlp5 + global max : 256-row blocks, double-buffered B ----------------
// Epilogue: warp-level shfl col-max -> relu -> atomicMax straight into d_g
// (no block reduce, no partial buffer, no extra barriers).
__global__ void __launch_bounds__(512) k_mlp5max() {
    extern __shared__ __half sh5[];
    __half* s_a = sh5;                        // 256*200

    int t = threadIdx.x, lane = t & 31, w = t >> 5;
    int wm = w >> 2, wn = w & 3;
    size_t m0 = (size_t)blockIdx.x * 256;
    uint32_t ab = smem_u32(s_a);
    uint32_t bb0 = ab + 51200 * 2, bb1 = ab + 76800 * 2;

    // stage A (once): 256 rows x 24 16B-chunks
    for (int i = t; i < 6144; i += 512) {
        int r = i / 24, c = i % 24;
        const __half* src = (c < 8) ? d_xgmh + (m0 + r) * 64 + c * 8
                                    : d_h4h + (m0 + r) * 128 + (c - 8) * 8;
        cp16(ab + (uint32_t)(r * 200 + c * 8) * 2, src);
    }
    for (int i = t; i < 3072; i += 512) {
        int r = i / 24, c = i % 24;
        cp16(bb0 + (uint32_t)(r * 200 + c * 8) * 2, d_w5h + (size_t)r * 192 + c * 8);
    }
    CP_COMMIT();
    for (int i = t; i < 3072; i += 512) {
        int r = i / 24, c = i % 24;
        cp16(bb1 + (uint32_t)(r * 200 + c * 8) * 2, d_w5h + (size_t)(128 + r) * 192 + c * 8);
    }
    CP_COMMIT();

    for (int nt = 0; nt < 8; nt++) {
        if (nt >= 6) CP_WAIT0(); else CP_WAIT1();   // nt>=6: last group must be fully in
        __syncthreads();
        uint32_t cur = (nt & 1) ? bb1 : bb0;

        float c_[4][4][4];
#pragma unroll
        for (int i = 0; i < 4; i++)
#pragma unroll
            for (int j = 0; j < 4; j++)
#pragma unroll
                for (int r = 0; r < 4; r++) c_[i][j][r] = 0.f;

#pragma unroll
        for (int q = 0; q < 12; q++) {
            uint32_t a_[4][4], b_[2][4];
#pragma unroll
            for (int mt = 0; mt < 4; mt++) {
                uint32_t row = 64 * wm + 16 * mt + (lane & 15);
                uint32_t kh  = q * 16 + 8 * (lane >> 4);
                ldsm4(a_[mt][0], a_[mt][1], a_[mt][2], a_[mt][3],
                      ab + (row * 200 + kh) * 2);
            }
#pragma unroll
            for (int p = 0; p < 2; p++) {
                uint32_t bn = 32 * wn + 16 * p + (lane & 7) + 8 * (lane >> 4);
                uint32_t kh = q * 16 + 8 * ((lane >> 3) & 1);
                ldsm4(b_[p][0], b_[p][1], b_[p][2], b_[p][3],
                      cur + (bn * 200 + kh) * 2);
            }
#pragma unroll
            for (int mt = 0; mt < 4; mt++) {
                mma_f16(c_[mt][0], a_[mt][0], a_[mt][1], a_[mt][2], a_[mt][3], b_[0][0], b_[0][1]);
                mma_f16(c_[mt][1], a_[mt][0], a_[mt][1], a_[mt][2], a_[mt][3], b_[0][2], b_[0][3]);
                mma_f16(c_[mt][2], a_[mt][0], a_[mt][1], a_[mt][2], a_[mt][3], b_[1][0], b_[1][1]);
                mma_f16(c_[mt][3], a_[mt][0], a_[mt][1], a_[mt][2], a_[mt][3], b_[1][2], b_[1][3]);
            }
        }
        __syncthreads();     // all warps done reading cur

        if (nt < 6) {        // prefetch nt+2 into the buffer just freed
            uint32_t nxt = (nt & 1) ? bb1 : bb0;
            for (int i = t; i < 3072; i += 512) {
                int r = i / 24, c = i % 24;
                cp16(nxt + (uint32_t)(r * 200 + c * 8) * 2,
                     d_w5h + (size_t)((nt + 2) * 128 + r) * 192 + c * 8);
            }
            CP_COMMIT();
        }

        // epilogue: col-max over warp's 64 rows, relu, atomicMax into d_g
        float cm[8];
#pragma unroll
        for (int nq = 0; nq < 4; nq++) {
            float v0 = fmaxf(fmaxf(c_[0][nq][0], c_[0][nq][2]),
                             fmaxf(c_[1][nq][0], c_[1][nq][2]));
            v0 = fmaxf(v0, fmaxf(fmaxf(c_[2][nq][0], c_[2][nq][2]),
                                 fmaxf(c_[3][nq][0], c_[3][nq][2])));
            float v1 = fmaxf(fmaxf(c_[0][nq][1], c_[0][nq][3]),
                             fmaxf(c_[1][nq][1], c_[1][nq][3]));
            v1 = fmaxf(v1, fmaxf(fmaxf(c_[2][nq][1], c_[2][nq][3]),
                                 fmaxf(c_[3][nq][1], c_[3][nq][3])));
            cm[nq * 2 + 0] = v0;
            cm[nq * 2 + 1] = v1;
        }
#pragma unroll
        for (int off = 4; off < 32; off <<= 1)
#pragma unroll
            for (int j = 0; j < 8; j++)
                cm[j] = fmaxf(cm[j], __shfl_xor_sync(0xffffffffu, cm[j], off));
        if (lane < 4) {
            int colbase = nt * 128 + wn * 32 + 2 * lane;
#pragma unroll
            for (int nq = 0; nq < 4; nq++) {
                atomicMax((int*)&d_g[colbase + nq * 8],
                          __float_as_int(fmaxf(cm[2 * nq], 0.0f)));
                atomicMax((int*)&d_g[colbase + nq * 8 + 1],
                          __float_as_int(fmaxf(cm[2 * nq + 1], 0.0f)));
            }
        }
    }
}

// ---------------- head: 3 small GEMVs ----------------
__device__ __forceinline__ float blk_dot_reduce(float a) {
#pragma unroll
    for (int o = 16; o; o >>= 1) a += __shfl_xor_sync(0xffffffffu, a, o);
    __shared__ float s[4];
    int t = threadIdx.x;
    if ((t & 31) == 0) s[t >> 5] = a;
    __syncthreads();
    return s[0] + s[1] + s[2] + s[3];
}

__global__ void __launch_bounds__(128) k_head1(const float* __restrict__ wf1) {
    int t = threadIdx.x;
    const float4* wr = (const float4*)&wf1[(size_t)blockIdx.x * 1024];
    const float4* gr = (const float4*)d_g;
    float a = 0.f;
    for (int k = t; k < 256; k += 128) {
        float4 wv = __ldg(&wr[k]); float4 gv = gr[k];
        a += wv.x * gv.x + wv.y * gv.y + wv.z * gv.z + wv.w * gv.w;
    }
    float r = blk_dot_reduce(a);
    if (t == 0) d_f1[blockIdx.x] = fmaxf(r, 0.0f);
}

__global__ void __launch_bounds__(128) k_head2(const float* __restrict__ wf2) {
    int t = threadIdx.x;
    const float4* wr = (const float4*)&wf2[(size_t)blockIdx.x * 512];
    const float4* gr = (const float4*)d_f1;
    float a = 0.f;
    if (t < 128) {
        float4 wv = __ldg(&wr[t]); float4 gv = gr[t];
        a = wv.x * gv.x + wv.y * gv.y + wv.z * gv.z + wv.w * gv.w;
    }
    float r = blk_dot_reduce(a);
    if (t == 0) d_f2[blockIdx.x] = fmaxf(r, 0.0f);
}

__global__ void __launch_bounds__(128) k_head3(const float* __restrict__ wf3,
                                               float* __restrict__ out) {
    int t = threadIdx.x;
    const float4* wr = (const float4*)&wf3[(size_t)blockIdx.x * 256];
    const float4* gr = (const float4*)d_f2;
    float a = 0.f;
    if (t < 64) {
        float4 wv = __ldg(&wr[t]); float4 gv = gr[t];
        a = wv.x * gv.x + wv.y * gv.y + wv.z * gv.z + wv.w * gv.w;
    }
    float r = blk_dot_reduce(a);
    if (t == 0) out[blockIdx.x] = r;
}

// ---------------- launch ----------------
extern "C" void kernel_launch(void* const* d_in, const int* in_sizes, int n_in,
                              void* d_out, int out_size) {
    const float* x       = (const float*)d_in[0];
    const int*   indices = (const int*)d_in[2];   // indptr (d_in[1]) fixed K=16
    const float* w1  = (const float*)d_in[3];
    const float* w2  = (const float*)d_in[4];
    const float* w3  = (const float*)d_in[5];
    const float* w4  = (const float*)d_in[6];
    const float* w5  = (const float*)d_in[7];
    const float* wf1 = (const float*)d_in[8];
    const float* wf2 = (const float*)d_in[9];
    const float* wf3 = (const float*)d_in[10];
    float* out = (float*)d_out;

    const int SMEM_F = 35840 * 2 + 576 * 4;           // 74,176 B
    const int SMEM_5 = (51200 + 2 * 25600) * 2;       // 204,800 B
    cudaFuncSetAttribute(k_mlp1234, cudaFuncAttributeMaxDynamicSharedMemorySize, SMEM_F);
    cudaFuncSetAttribute(k_mlp5max, cudaFuncAttributeMaxDynamicSharedMemorySize, SMEM_5);

    k_prep   <<<836, 256>>>(w2, w3, w4, w5);
    k_mlp1234<<<NPTS / 128, 256, SMEM_F>>>(x, w1);
    k_gmax   <<<NPTS / 8,   256>>>(indices);
    k_mlp5max<<<NPTS / 256, 512, SMEM_5>>>();
    k_head1  <<<512, 128>>>(wf1);
    k_head2  <<<256, 128>>>(wf2);
    k_head3  <<<40,  128>>>(wf3, out);
}

// round 8
// speedup vs baseline: 15.5162x; 1.0328x over previous
#include <cuda_runtime.h>
#include <cuda_fp16.h>
#include <cstdint>

#define NPTS 262144

// ---------------- device scratch (no allocations allowed) ----------------
__device__ __half d_h2h [NPTS * 64];      // after mlp1+mlp2 (relu, fp16)
__device__ __half d_xgmh[NPTS * 64];      // neighbor max-pooled (fp16)
__device__ __half d_h4h [NPTS * 128];     // after mlp3+mlp4 (relu, fp16)
__device__ __half d_w2h [64 * 64];
__device__ __half d_w3h [64 * 64];
__device__ __half d_w4h [128 * 64];
__device__ __half d_w5h [1024 * 192];
__device__ float  d_g  [1024];            // global max (post-relu), atomicMax target
__device__ float  d_f1 [512];
__device__ float  d_f2 [256];

// ---------------- helpers ----------------
__device__ __forceinline__ uint32_t smem_u32(const void* p) {
    uint32_t a;
    asm("{ .reg .u64 t; cvta.to.shared.u64 t, %1; cvt.u32.u64 %0, t; }"
        : "=r"(a) : "l"(p));
    return a;
}
__device__ __forceinline__ void cp16(uint32_t dst, const void* src) {
    asm volatile("cp.async.cg.shared.global [%0], [%1], 16;"
                 :: "r"(dst), "l"(src) : "memory");
}
#define CP_COMMIT() asm volatile("cp.async.commit_group;" ::: "memory")
#define CP_WAIT0()  asm volatile("cp.async.wait_group 0;" ::: "memory")

__device__ __forceinline__ void ldsm4(uint32_t& r0, uint32_t& r1,
                                      uint32_t& r2, uint32_t& r3, uint32_t addr) {
    asm volatile("ldmatrix.sync.aligned.m8n8.x4.shared.b16 {%0,%1,%2,%3}, [%4];"
                 : "=r"(r0), "=r"(r1), "=r"(r2), "=r"(r3) : "r"(addr));
}
__device__ __forceinline__ void mma_f16(float* c, uint32_t a0, uint32_t a1,
                                        uint32_t a2, uint32_t a3,
                                        uint32_t b0, uint32_t b1) {
    asm volatile(
        "mma.sync.aligned.m16n8k16.row.col.f32.f16.f16.f32 "
        "{%0,%1,%2,%3}, {%4,%5,%6,%7}, {%8,%9}, {%0,%1,%2,%3};"
        : "+f"(c[0]), "+f"(c[1]), "+f"(c[2]), "+f"(c[3])
        : "r"(a0), "r"(a1), "r"(a2), "r"(a3), "r"(b0), "r"(b1));
}
__device__ __forceinline__ uint32_t ph2_relu(float x, float y) {
    __half2 h = __floats2half2_rn(fmaxf(x, 0.f), fmaxf(y, 0.f));
    return *reinterpret_cast<uint32_t*>(&h);
}

// B stationed in smem rows [n x 72-stride]; GEMM over K=64, N=64
__device__ __forceinline__ void gemm64(uint32_t sbase, const uint32_t (&a)[4][4],
                                       float (&c)[8][4], int lane) {
#pragma unroll
    for (int j = 0; j < 8; j++)
#pragma unroll
        for (int r = 0; r < 4; r++) c[j][r] = 0.f;
#pragma unroll
    for (int q = 0; q < 4; q++) {
#pragma unroll
        for (int jp = 0; jp < 4; jp++) {
            uint32_t B0, B1, B2, B3;
            uint32_t bn = 16 * jp + (lane & 7) + 8 * (lane >> 4);
            uint32_t bk = q * 16 + 8 * ((lane >> 3) & 1);
            ldsm4(B0, B1, B2, B3, sbase + (bn * 72 + bk) * 2);
            mma_f16(c[2 * jp],     a[q][0], a[q][1], a[q][2], a[q][3], B0, B1);
            mma_f16(c[2 * jp + 1], a[q][0], a[q][1], a[q][2], a[q][3], B2, B3);
        }
    }
}
__device__ __forceinline__ void pack_relu(const float (&c)[8][4], uint32_t (&a)[4][4]) {
#pragma unroll
    for (int q = 0; q < 4; q++) {
        a[q][0] = ph2_relu(c[2 * q][0],     c[2 * q][1]);
        a[q][1] = ph2_relu(c[2 * q][2],     c[2 * q][3]);
        a[q][2] = ph2_relu(c[2 * q + 1][0], c[2 * q + 1][1]);
        a[q][3] = ph2_relu(c[2 * q + 1][2], c[2 * q + 1][3]);
    }
}

// ---------------- prep: w2..w5 fp32->fp16 + zero d_g (one kernel) ----------------
__global__ void __launch_bounds__(256) k_prep(const float* __restrict__ w2,
                                              const float* __restrict__ w3,
                                              const float* __restrict__ w4,
                                              const float* __restrict__ w5) {
    int b = blockIdx.x, t = threadIdx.x;
    if (b < 768) {
        int i = b * 256 + t;                       // 196608 w5 elements
        d_w5h[i] = __float2half_rn(w5[i]);
    } else if (b < 832) {
        int i = (b - 768) * 256 + t;               // 16384 w2/w3/w4 elements
        if (i < 4096)      d_w2h[i]        = __float2half_rn(w2[i]);
        else if (i < 8192) d_w3h[i - 4096] = __float2half_rn(w3[i - 4096]);
        else               d_w4h[i - 8192] = __float2half_rn(w4[i - 8192]);
    } else {
        d_g[(b - 832) * 256 + t] = 0.0f;           // 1024 (relu output >= 0)
    }
}

// ---------------- fused mlp1..mlp4 : x[N,3] -> h2[N,64], h4[N,128] ----------------
__global__ void __launch_bounds__(256, 2) k_mlp1234(const float* __restrict__ x,
                                                    const float* __restrict__ w1) {
    extern __shared__ __half sh[];
    const int OFF_W2 = 0, OFF_W3 = 4608, OFF_W4 = 9216, OFF_OUT = 18432;
    __half* s_out = sh + OFF_OUT;                   // 128*136
    float*  s_xf  = (float*)(sh + 35840);           // 128*3
    float*  s_w1f = s_xf + 384;                     // 64*3

    int t = threadIdx.x, lane = t & 31, w = t >> 5;
    int g = lane >> 2, tig = lane & 3;
    size_t p0 = (size_t)blockIdx.x * 128;
    uint32_t sb = smem_u32(sh);

    for (int i = t; i < 512; i += 256) {
        int r = i >> 3, c = i & 7;
        cp16(sb + (uint32_t)(OFF_W2 + r * 72 + c * 8) * 2, d_w2h + r * 64 + c * 8);
        cp16(sb + (uint32_t)(OFF_W3 + r * 72 + c * 8) * 2, d_w3h + r * 64 + c * 8);
    }
    for (int i = t; i < 1024; i += 256) {
        int r = i >> 3, c = i & 7;
        cp16(sb + (uint32_t)(OFF_W4 + r * 72 + c * 8) * 2, d_w4h + r * 64 + c * 8);
    }
    for (int i = t; i < 384; i += 256) s_xf[i] = x[p0 * 3 + i];
    if (t < 192) s_w1f[t] = w1[t];
    CP_COMMIT(); CP_WAIT0();
    __syncthreads();

    // mlp1: this thread's 32 h1 values straight into a-frag layout
    int r0 = 16 * w + g;
    float xa0 = s_xf[r0 * 3], xa1 = s_xf[r0 * 3 + 1], xa2 = s_xf[r0 * 3 + 2];
    float xb0 = s_xf[(r0 + 8) * 3], xb1 = s_xf[(r0 + 8) * 3 + 1], xb2 = s_xf[(r0 + 8) * 3 + 2];
    uint32_t a1h[4][4];
#pragma unroll
    for (int q = 0; q < 4; q++) {
        int f0 = 16 * q + 2 * tig;
        int f2 = f0 + 8;
#define DOT3(f, u0, u1, u2) \
        fmaf(s_w1f[(f)*3+2], u2, fmaf(s_w1f[(f)*3+1], u1, s_w1f[(f)*3] * u0))
        a1h[q][0] = ph2_relu(DOT3(f0, xa0, xa1, xa2), DOT3(f0 + 1, xa0, xa1, xa2));
        a1h[q][1] = ph2_relu(DOT3(f0, xb0, xb1, xb2), DOT3(f0 + 1, xb0, xb1, xb2));
        a1h[q][2] = ph2_relu(DOT3(f2, xa0, xa1, xa2), DOT3(f2 + 1, xa0, xa1, xa2));
        a1h[q][3] = ph2_relu(DOT3(f2, xb0, xb1, xb2), DOT3(f2 + 1, xb0, xb1, xb2));
#undef DOT3
    }

    // GEMM2: h2 = relu(h1 @ w2^T)
    float c2[8][4];
    uint32_t a2h[4][4];
    gemm64(sb + OFF_W2 * 2, a1h, c2, lane);
    pack_relu(c2, a2h);

#pragma unroll
    for (int q = 0; q < 4; q++) {
        int c0 = 16 * q + 2 * tig, cc2 = c0 + 8;
        *(uint32_t*)&s_out[r0 * 136 + c0]        = a2h[q][0];
        *(uint32_t*)&s_out[(r0 + 8) * 136 + c0]  = a2h[q][1];
        *(uint32_t*)&s_out[r0 * 136 + cc2]       = a2h[q][2];
        *(uint32_t*)&s_out[(r0 + 8) * 136 + cc2] = a2h[q][3];
    }
    __syncthreads();
    for (int i = t; i < 1024; i += 256) {
        int r = i >> 3, c = i & 7;
        *(uint4*)&d_h2h[(p0 + r) * 64 + c * 8] = *(uint4*)&s_out[r * 136 + c * 8];
    }
    __syncthreads();   // s_out reused for h4

    // GEMM3: h3 = relu(h2 @ w3^T)
    float c3[8][4];
    uint32_t a3h[4][4];
    gemm64(sb + OFF_W3 * 2, a2h, c3, lane);
    pack_relu(c3, a3h);

    // GEMM4: h4 = relu(h3 @ w4^T), N=128 in two halves
#pragma unroll
    for (int nh = 0; nh < 2; nh++) {
        float c4[8][4];
#pragma unroll
        for (int j = 0; j < 8; j++)
#pragma unroll
            for (int r = 0; r < 4; r++) c4[j][r] = 0.f;
#pragma unroll
        for (int q = 0; q < 4; q++) {
#pragma unroll
            for (int jp = 0; jp < 4; jp++) {
                uint32_t B0, B1, B2, B3;
                uint32_t bn = 64 * nh + 16 * jp + (lane & 7) + 8 * (lane >> 4);
                uint32_t bk = q * 16 + 8 * ((lane >> 3) & 1);
                ldsm4(B0, B1, B2, B3, sb + (OFF_W4 + bn * 72 + bk) * 2);
                mma_f16(c4[2 * jp],     a3h[q][0], a3h[q][1], a3h[q][2], a3h[q][3], B0, B1);
                mma_f16(c4[2 * jp + 1], a3h[q][0], a3h[q][1], a3h[q][2], a3h[q][3], B2, B3);
            }
        }
#pragma unroll
        for (int j2 = 0; j2 < 8; j2++) {
            int coln = 64 * nh + 8 * j2 + 2 * tig;
            *(uint32_t*)&s_out[r0 * 136 + coln]       = ph2_relu(c4[j2][0], c4[j2][1]);
            *(uint32_t*)&s_out[(r0 + 8) * 136 + coln] = ph2_relu(c4[j2][2], c4[j2][3]);
        }
    }
    __syncthreads();
    for (int i = t; i < 2048; i += 256) {
        int r = i >> 4, c = i & 15;
        *(uint4*)&d_h4h[(p0 + r) * 128 + c * 8] = *(uint4*)&s_out[r * 136 + c * 8];
    }
}

// ---------------- graph max pooling (K=16), fp16, 32 threads/point ----------------
__global__ void __launch_bounds__(256) k_gmax(const int* __restrict__ indices) {
    __shared__ int s_idx[8][16];
    int t = threadIdx.x, lane = t & 31, pl = t >> 5;
    int base = blockIdx.x * 8;
    if (t < 128) s_idx[t >> 4][t & 15] = indices[base * 16 + t];
    __syncthreads();

    __half2 m = __float2half2_rn(0.0f);   // h2 >= 0
    const __half2* h2 = (const __half2*)d_h2h;
#pragma unroll
    for (int j = 0; j < 16; j++) {
        unsigned off = (unsigned)s_idx[pl][j] * 32u + (unsigned)lane;
        m = __hmax2(m, h2[off]);
    }
    ((__half2*)d_xgmh)[(unsigned)(base + pl) * 32u + lane] = m;
}

// ---------------- mlp5 + global max : 128-row blocks, 2 CTAs/SM ----------------
// A (50KB) + single B buffer (50KB) -> 100KB/CTA -> 2 CTAs/SM; the co-resident
// CTA's HMMA stream covers this CTA's barriers, B staging, and epilogue.
// Epilogue: warp shfl col-max -> relu -> atomicMax into d_g.
__global__ void __launch_bounds__(256, 2) k_mlp5max() {
    extern __shared__ __half sh5[];
    __half* s_a = sh5;                        // 128*200
    __half* s_b = sh5 + 25600;                // 128*200

    int t = threadIdx.x, lane = t & 31, w = t >> 5;
    int wm = w >> 2, wn = w & 3;
    size_t m0 = (size_t)blockIdx.x * 128;
    uint32_t ab = smem_u32(s_a), bb = smem_u32(s_b);

    // stage A (once) + B tile 0
    for (int i = t; i < 3072; i += 256) {
        int r = i / 24, c = i % 24;
        const __half* src = (c < 8) ? d_xgmh + (m0 + r) * 64 + c * 8
                                    : d_h4h + (m0 + r) * 128 + (c - 8) * 8;
        cp16(ab + (uint32_t)(r * 200 + c * 8) * 2, src);
    }
    for (int i = t; i < 3072; i += 256) {
        int r = i / 24, c = i % 24;
        cp16(bb + (uint32_t)(r * 200 + c * 8) * 2, d_w5h + (size_t)r * 192 + c * 8);
    }
    CP_COMMIT(); CP_WAIT0();
    __syncthreads();

    for (int nt = 0; nt < 8; nt++) {
        float c_[4][4][4];
#pragma unroll
        for (int i = 0; i < 4; i++)
#pragma unroll
            for (int j = 0; j < 4; j++)
#pragma unroll
                for (int r = 0; r < 4; r++) c_[i][j][r] = 0.f;

#pragma unroll
        for (int q = 0; q < 12; q++) {
            uint32_t a_[4][4], b_[2][4];
#pragma unroll
            for (int mt = 0; mt < 4; mt++) {
                uint32_t row = 64 * wm + 16 * mt + (lane & 15);
                uint32_t kh  = q * 16 + 8 * (lane >> 4);
                ldsm4(a_[mt][0], a_[mt][1], a_[mt][2], a_[mt][3],
                      ab + (row * 200 + kh) * 2);
            }
#pragma unroll
            for (int p = 0; p < 2; p++) {
                uint32_t bn = 32 * wn + 16 * p + (lane & 7) + 8 * (lane >> 4);
                uint32_t kh = q * 16 + 8 * ((lane >> 3) & 1);
                ldsm4(b_[p][0], b_[p][1], b_[p][2], b_[p][3],
                      bb + (bn * 200 + kh) * 2);
            }
#pragma unroll
            for (int mt = 0; mt < 4; mt++) {
                mma_f16(c_[mt][0], a_[mt][0], a_[mt][1], a_[mt][2], a_[mt][3], b_[0][0], b_[0][1]);
                mma_f16(c_[mt][1], a_[mt][0], a_[mt][1], a_[mt][2], a_[mt][3], b_[0][2], b_[0][3]);
                mma_f16(c_[mt][2], a_[mt][0], a_[mt][1], a_[mt][2], a_[mt][3], b_[1][0], b_[1][1]);
                mma_f16(c_[mt][3], a_[mt][0], a_[mt][1], a_[mt][2], a_[mt][3], b_[1][2], b_[1][3]);
            }
        }
        __syncthreads();     // all warps done reading s_b

        if (nt < 7) {        // prefetch next B tile; overlaps epilogue
            for (int i = t; i < 3072; i += 256) {
                int r = i / 24, c = i % 24;
                cp16(bb + (uint32_t)(r * 200 + c * 8) * 2,
                     d_w5h + (size_t)((nt + 1) * 128 + r) * 192 + c * 8);
            }
            CP_COMMIT();
        }

        // epilogue: col-max over warp's 64 rows, relu, atomicMax into d_g
        float cm[8];
#pragma unroll
        for (int nq = 0; nq < 4; nq++) {
            float v0 = fmaxf(fmaxf(c_[0][nq][0], c_[0][nq][2]),
                             fmaxf(c_[1][nq][0], c_[1][nq][2]));
            v0 = fmaxf(v0, fmaxf(fmaxf(c_[2][nq][0], c_[2][nq][2]),
                                 fmaxf(c_[3][nq][0], c_[3][nq][2])));
            float v1 = fmaxf(fmaxf(c_[0][nq][1], c_[0][nq][3]),
                             fmaxf(c_[1][nq][1], c_[1][nq][3]));
            v1 = fmaxf(v1, fmaxf(fmaxf(c_[2][nq][1], c_[2][nq][3]),
                                 fmaxf(c_[3][nq][1], c_[3][nq][3])));
            cm[nq * 2 + 0] = v0;
            cm[nq * 2 + 1] = v1;
        }
#pragma unroll
        for (int off = 4; off < 32; off <<= 1)
#pragma unroll
            for (int j = 0; j < 8; j++)
                cm[j] = fmaxf(cm[j], __shfl_xor_sync(0xffffffffu, cm[j], off));
        if (lane < 4) {
            int colbase = nt * 128 + wn * 32 + 2 * lane;
#pragma unroll
            for (int nq = 0; nq < 4; nq++) {
                atomicMax((int*)&d_g[colbase + nq * 8],
                          __float_as_int(fmaxf(cm[2 * nq], 0.0f)));
                atomicMax((int*)&d_g[colbase + nq * 8 + 1],
                          __float_as_int(fmaxf(cm[2 * nq + 1], 0.0f)));
            }
        }
        if (nt < 7) CP_WAIT0();
        __syncthreads();     // s_b refilled, safe for next iteration
    }
}

// ---------------- head: 3 small GEMVs ----------------
__device__ __forceinline__ float blk_dot_reduce(float a) {
#pragma unroll
    for (int o = 16; o; o >>= 1) a += __shfl_xor_sync(0xffffffffu, a, o);
    __shared__ float s[4];
    int t = threadIdx.x;
    if ((t & 31) == 0) s[t >> 5] = a;
    __syncthreads();
    return s[0] + s[1] + s[2] + s[3];
}

__global__ void __launch_bounds__(128) k_head1(const float* __restrict__ wf1) {
    int t = threadIdx.x;
    const float4* wr = (const float4*)&wf1[(size_t)blockIdx.x * 1024];
    const float4* gr = (const float4*)d_g;
    float a = 0.f;
    for (int k = t; k < 256; k += 128) {
        float4 wv = __ldg(&wr[k]); float4 gv = gr[k];
        a += wv.x * gv.x + wv.y * gv.y + wv.z * gv.z + wv.w * gv.w;
    }
    float r = blk_dot_reduce(a);
    if (t == 0) d_f1[blockIdx.x] = fmaxf(r, 0.0f);
}

__global__ void __launch_bounds__(128) k_head2(const float* __restrict__ wf2) {
    int t = threadIdx.x;
    const float4* wr = (const float4*)&wf2[(size_t)blockIdx.x * 512];
    const float4* gr = (const float4*)d_f1;
    float a = 0.f;
    if (t < 128) {
        float4 wv = __ldg(&wr[t]); float4 gv = gr[t];
        a = wv.x * gv.x + wv.y * gv.y + wv.z * gv.z + wv.w * gv.w;
    }
    float r = blk_dot_reduce(a);
    if (t == 0) d_f2[blockIdx.x] = fmaxf(r, 0.0f);
}

__global__ void __launch_bounds__(128) k_head3(const float* __restrict__ wf3,
                                               float* __restrict__ out) {
    int t = threadIdx.x;
    const float4* wr = (const float4*)&wf3[(size_t)blockIdx.x * 256];
    const float4* gr = (const float4*)d_f2;
    float a = 0.f;
    if (t < 64) {
        float4 wv = __ldg(&wr[t]); float4 gv = gr[t];
        a = wv.x * gv.x + wv.y * gv.y + wv.z * gv.z + wv.w * gv.w;
    }
    float r = blk_dot_reduce(a);
    if (t == 0) out[blockIdx.x] = r;
}

// ---------------- launch ----------------
extern "C" void kernel_launch(void* const* d_in, const int* in_sizes, int n_in,
                              void* d_out, int out_size) {
    const float* x       = (const float*)d_in[0];
    const int*   indices = (const int*)d_in[2];   // indptr (d_in[1]) fixed K=16
    const float* w1  = (const float*)d_in[3];
    const float* w2  = (const float*)d_in[4];
    const float* w3  = (const float*)d_in[5];
    const float* w4  = (const float*)d_in[6];
    const float* w5  = (const float*)d_in[7];
    const float* wf1 = (const float*)d_in[8];
    const float* wf2 = (const float*)d_in[9];
    const float* wf3 = (const float*)d_in[10];
    float* out = (float*)d_out;

    const int SMEM_F = 35840 * 2 + 576 * 4;           // 74,176 B
    const int SMEM_5 = 2 * 128 * 200 * 2;             // 102,400 B -> 2 CTAs/SM
    cudaFuncSetAttribute(k_mlp1234, cudaFuncAttributeMaxDynamicSharedMemorySize, SMEM_F);
    cudaFuncSetAttribute(k_mlp5max, cudaFuncAttributeMaxDynamicSharedMemorySize, SMEM_5);

    k_prep   <<<836, 256>>>(w2, w3, w4, w5);
    k_mlp1234<<<NPTS / 128, 256, SMEM_F>>>(x, w1);
    k_gmax   <<<NPTS / 8,   256>>>(indices);
    k_mlp5max<<<NPTS / 128, 256, SMEM_5>>>();
    k_head1  <<<512, 128>>>(wf1);
    k_head2  <<<256, 128>>>(wf2);
    k_head3  <<<40,  128>>>(wf3, out);
}

// round 9
// speedup vs baseline: 15.5960x; 1.0051x over previous
#include <cuda_runtime.h>
#include <cuda_fp16.h>
#include <cstdint>

#define NPTS 262144

// ---------------- device scratch (no allocations allowed) ----------------
__device__ __half d_h2h [NPTS * 64];      // after mlp1+mlp2 (relu, fp16)
__device__ __half d_xgmh[NPTS * 64];      // neighbor max-pooled (fp16)
__device__ __half d_h4h [NPTS * 128];     // after mlp3+mlp4 (relu, fp16)
__device__ __half d_w2h [64 * 64];
__device__ __half d_w3h [64 * 64];
__device__ __half d_w4h [128 * 64];
__device__ __half d_w5h [1024 * 192];
__device__ float  d_g  [1024];            // global max (post-relu), atomicMax target
__device__ float  d_f1 [512];
__device__ float  d_f2 [256];

// ---------------- helpers ----------------
__device__ __forceinline__ uint32_t smem_u32(const void* p) {
    uint32_t a;
    asm("{ .reg .u64 t; cvta.to.shared.u64 t, %1; cvt.u32.u64 %0, t; }"
        : "=r"(a) : "l"(p));
    return a;
}
__device__ __forceinline__ void cp16(uint32_t dst, const void* src) {
    asm volatile("cp.async.cg.shared.global [%0], [%1], 16;"
                 :: "r"(dst), "l"(src) : "memory");
}
#define CP_COMMIT() asm volatile("cp.async.commit_group;" ::: "memory")
#define CP_WAIT0()  asm volatile("cp.async.wait_group 0;" ::: "memory")

__device__ __forceinline__ void ldsm4(uint32_t& r0, uint32_t& r1,
                                      uint32_t& r2, uint32_t& r3, uint32_t addr) {
    asm volatile("ldmatrix.sync.aligned.m8n8.x4.shared.b16 {%0,%1,%2,%3}, [%4];"
                 : "=r"(r0), "=r"(r1), "=r"(r2), "=r"(r3) : "r"(addr));
}
__device__ __forceinline__ void mma_f16(float* c, uint32_t a0, uint32_t a1,
                                        uint32_t a2, uint32_t a3,
                                        uint32_t b0, uint32_t b1) {
    asm volatile(
        "mma.sync.aligned.m16n8k16.row.col.f32.f16.f16.f32 "
        "{%0,%1,%2,%3}, {%4,%5,%6,%7}, {%8,%9}, {%0,%1,%2,%3};"
        : "+f"(c[0]), "+f"(c[1]), "+f"(c[2]), "+f"(c[3])
        : "r"(a0), "r"(a1), "r"(a2), "r"(a3), "r"(b0), "r"(b1));
}
__device__ __forceinline__ uint32_t ph2_relu(float x, float y) {
    __half2 h = __floats2half2_rn(fmaxf(x, 0.f), fmaxf(y, 0.f));
    return *reinterpret_cast<uint32_t*>(&h);
}

// B stationed in smem rows [n x 72-stride]; GEMM over K=64, N=64
__device__ __forceinline__ void gemm64(uint32_t sbase, const uint32_t (&a)[4][4],
                                       float (&c)[8][4], int lane) {
#pragma unroll
    for (int j = 0; j < 8; j++)
#pragma unroll
        for (int r = 0; r < 4; r++) c[j][r] = 0.f;
#pragma unroll
    for (int q = 0; q < 4; q++) {
#pragma unroll
        for (int jp = 0; jp < 4; jp++) {
            uint32_t B0, B1, B2, B3;
            uint32_t bn = 16 * jp + (lane & 7) + 8 * (lane >> 4);
            uint32_t bk = q * 16 + 8 * ((lane >> 3) & 1);
            ldsm4(B0, B1, B2, B3, sbase + (bn * 72 + bk) * 2);
            mma_f16(c[2 * jp],     a[q][0], a[q][1], a[q][2], a[q][3], B0, B1);
            mma_f16(c[2 * jp + 1], a[q][0], a[q][1], a[q][2], a[q][3], B2, B3);
        }
    }
}
__device__ __forceinline__ void pack_relu(const float (&c)[8][4], uint32_t (&a)[4][4]) {
#pragma unroll
    for (int q = 0; q < 4; q++) {
        a[q][0] = ph2_relu(c[2 * q][0],     c[2 * q][1]);
        a[q][1] = ph2_relu(c[2 * q][2],     c[2 * q][3]);
        a[q][2] = ph2_relu(c[2 * q + 1][0], c[2 * q + 1][1]);
        a[q][3] = ph2_relu(c[2 * q + 1][2], c[2 * q + 1][3]);
    }
}

// ---------------- prep: w2..w5 fp32->fp16 + zero d_g (one kernel) ----------------
__global__ void __launch_bounds__(256) k_prep(const float* __restrict__ w2,
                                              const float* __restrict__ w3,
                                              const float* __restrict__ w4,
                                              const float* __restrict__ w5) {
    int b = blockIdx.x, t = threadIdx.x;
    if (b < 768) {
        int i = b * 256 + t;                       // 196608 w5 elements
        d_w5h[i] = __float2half_rn(w5[i]);
    } else if (b < 832) {
        int i = (b - 768) * 256 + t;               // 16384 w2/w3/w4 elements
        if (i < 4096)      d_w2h[i]        = __float2half_rn(w2[i]);
        else if (i < 8192) d_w3h[i - 4096] = __float2half_rn(w3[i - 4096]);
        else               d_w4h[i - 8192] = __float2half_rn(w4[i - 8192]);
    } else {
        d_g[(b - 832) * 256 + t] = 0.0f;           // 1024 (relu output >= 0)
    }
}

// ---------------- fused mlp1..mlp4 : x[N,3] -> h2[N,64], h4[N,128] ----------------
__global__ void __launch_bounds__(256, 2) k_mlp1234(const float* __restrict__ x,
                                                    const float* __restrict__ w1) {
    extern __shared__ __half sh[];
    const int OFF_W2 = 0, OFF_W3 = 4608, OFF_W4 = 9216, OFF_OUT = 18432;
    __half* s_out = sh + OFF_OUT;                   // 128*136
    float*  s_xf  = (float*)(sh + 35840);           // 128*3
    float*  s_w1f = s_xf + 384;                     // 64*3

    int t = threadIdx.x, lane = t & 31, w = t >> 5;
    int g = lane >> 2, tig = lane & 3;
    size_t p0 = (size_t)blockIdx.x * 128;
    uint32_t sb = smem_u32(sh);

    for (int i = t; i < 512; i += 256) {
        int r = i >> 3, c = i & 7;
        cp16(sb + (uint32_t)(OFF_W2 + r * 72 + c * 8) * 2, d_w2h + r * 64 + c * 8);
        cp16(sb + (uint32_t)(OFF_W3 + r * 72 + c * 8) * 2, d_w3h + r * 64 + c * 8);
    }
    for (int i = t; i < 1024; i += 256) {
        int r = i >> 3, c = i & 7;
        cp16(sb + (uint32_t)(OFF_W4 + r * 72 + c * 8) * 2, d_w4h + r * 64 + c * 8);
    }
    for (int i = t; i < 384; i += 256) s_xf[i] = x[p0 * 3 + i];
    if (t < 192) s_w1f[t] = w1[t];
    CP_COMMIT(); CP_WAIT0();
    __syncthreads();

    // mlp1: this thread's 32 h1 values straight into a-frag layout
    int r0 = 16 * w + g;
    float xa0 = s_xf[r0 * 3], xa1 = s_xf[r0 * 3 + 1], xa2 = s_xf[r0 * 3 + 2];
    float xb0 = s_xf[(r0 + 8) * 3], xb1 = s_xf[(r0 + 8) * 3 + 1], xb2 = s_xf[(r0 + 8) * 3 + 2];
    uint32_t a1h[4][4];
#pragma unroll
    for (int q = 0; q < 4; q++) {
        int f0 = 16 * q + 2 * tig;
        int f2 = f0 + 8;
#define DOT3(f, u0, u1, u2) \
        fmaf(s_w1f[(f)*3+2], u2, fmaf(s_w1f[(f)*3+1], u1, s_w1f[(f)*3] * u0))
        a1h[q][0] = ph2_relu(DOT3(f0, xa0, xa1, xa2), DOT3(f0 + 1, xa0, xa1, xa2));
        a1h[q][1] = ph2_relu(DOT3(f0, xb0, xb1, xb2), DOT3(f0 + 1, xb0, xb1, xb2));
        a1h[q][2] = ph2_relu(DOT3(f2, xa0, xa1, xa2), DOT3(f2 + 1, xa0, xa1, xa2));
        a1h[q][3] = ph2_relu(DOT3(f2, xb0, xb1, xb2), DOT3(f2 + 1, xb0, xb1, xb2));
#undef DOT3
    }

    // GEMM2: h2 = relu(h1 @ w2^T)
    float c2[8][4];
    uint32_t a2h[4][4];
    gemm64(sb + OFF_W2 * 2, a1h, c2, lane);
    pack_relu(c2, a2h);

#pragma unroll
    for (int q = 0; q < 4; q++) {
        int c0 = 16 * q + 2 * tig, cc2 = c0 + 8;
        *(uint32_t*)&s_out[r0 * 136 + c0]        = a2h[q][0];
        *(uint32_t*)&s_out[(r0 + 8) * 136 + c0]  = a2h[q][1];
        *(uint32_t*)&s_out[r0 * 136 + cc2]       = a2h[q][2];
        *(uint32_t*)&s_out[(r0 + 8) * 136 + cc2] = a2h[q][3];
    }
    __syncthreads();
    for (int i = t; i < 1024; i += 256) {
        int r = i >> 3, c = i & 7;
        *(uint4*)&d_h2h[(p0 + r) * 64 + c * 8] = *(uint4*)&s_out[r * 136 + c * 8];
    }
    __syncthreads();   // s_out reused for h4

    // GEMM3: h3 = relu(h2 @ w3^T)
    float c3[8][4];
    uint32_t a3h[4][4];
    gemm64(sb + OFF_W3 * 2, a2h, c3, lane);
    pack_relu(c3, a3h);

    // GEMM4: h4 = relu(h3 @ w4^T), N=128 in two halves
#pragma unroll
    for (int nh = 0; nh < 2; nh++) {
        float c4[8][4];
#pragma unroll
        for (int j = 0; j < 8; j++)
#pragma unroll
            for (int r = 0; r < 4; r++) c4[j][r] = 0.f;
#pragma unroll
        for (int q = 0; q < 4; q++) {
#pragma unroll
            for (int jp = 0; jp < 4; jp++) {
                uint32_t B0, B1, B2, B3;
                uint32_t bn = 64 * nh + 16 * jp + (lane & 7) + 8 * (lane >> 4);
                uint32_t bk = q * 16 + 8 * ((lane >> 3) & 1);
                ldsm4(B0, B1, B2, B3, sb + (OFF_W4 + bn * 72 + bk) * 2);
                mma_f16(c4[2 * jp],     a3h[q][0], a3h[q][1], a3h[q][2], a3h[q][3], B0, B1);
                mma_f16(c4[2 * jp + 1], a3h[q][0], a3h[q][1], a3h[q][2], a3h[q][3], B2, B3);
            }
        }
#pragma unroll
        for (int j2 = 0; j2 < 8; j2++) {
            int coln = 64 * nh + 8 * j2 + 2 * tig;
            *(uint32_t*)&s_out[r0 * 136 + coln]       = ph2_relu(c4[j2][0], c4[j2][1]);
            *(uint32_t*)&s_out[(r0 + 8) * 136 + coln] = ph2_relu(c4[j2][2], c4[j2][3]);
        }
    }
    __syncthreads();
    for (int i = t; i < 2048; i += 256) {
        int r = i >> 4, c = i & 15;
        *(uint4*)&d_h4h[(p0 + r) * 128 + c * 8] = *(uint4*)&s_out[r * 136 + c * 8];
    }
}

// ---------------- graph max pooling (K=16), fp16, 32 threads/point ----------------
__global__ void __launch_bounds__(256) k_gmax(const int* __restrict__ indices) {
    __shared__ int s_idx[8][16];
    int t = threadIdx.x, lane = t & 31, pl = t >> 5;
    int base = blockIdx.x * 8;
    if (t < 128) s_idx[t >> 4][t & 15] = indices[base * 16 + t];
    __syncthreads();

    __half2 m = __float2half2_rn(0.0f);   // h2 >= 0
    const __half2* h2 = (const __half2*)d_h2h;
#pragma unroll
    for (int j = 0; j < 16; j++) {
        unsigned off = (unsigned)s_idx[pl][j] * 32u + (unsigned)lane;
        m = __hmax2(m, h2[off]);
    }
    ((__half2*)d_xgmh)[(unsigned)(base + pl) * 32u + lane] = m;
}

// ---------------- mlp5 + global max : 128-row blocks, 2 CTAs/SM ----------------
// A (50KB) + single B buffer (50KB) -> 100KB/CTA -> 2 CTAs/SM; the co-resident
// CTA's HMMA stream covers this CTA's barriers, B staging, and epilogue.
// Epilogue: warp shfl col-max -> relu -> atomicMax into d_g.
__global__ void __launch_bounds__(256, 2) k_mlp5max() {
    extern __shared__ __half sh5[];
    __half* s_a = sh5;                        // 128*200
    __half* s_b = sh5 + 25600;                // 128*200

    int t = threadIdx.x, lane = t & 31, w = t >> 5;
    int wm = w >> 2, wn = w & 3;
    size_t m0 = (size_t)blockIdx.x * 128;
    uint32_t ab = smem_u32(s_a), bb = smem_u32(s_b);

    // stage A (once) + B tile 0
    for (int i = t; i < 3072; i += 256) {
        int r = i / 24, c = i % 24;
        const __half* src = (c < 8) ? d_xgmh + (m0 + r) * 64 + c * 8
                                    : d_h4h + (m0 + r) * 128 + (c - 8) * 8;
        cp16(ab + (uint32_t)(r * 200 + c * 8) * 2, src);
    }
    for (int i = t; i < 3072; i += 256) {
        int r = i / 24, c = i % 24;
        cp16(bb + (uint32_t)(r * 200 + c * 8) * 2, d_w5h + (size_t)r * 192 + c * 8);
    }
    CP_COMMIT(); CP_WAIT0();
    __syncthreads();

    for (int nt = 0; nt < 8; nt++) {
        float c_[4][4][4];
#pragma unroll
        for (int i = 0; i < 4; i++)
#pragma unroll
            for (int j = 0; j < 4; j++)
#pragma unroll
                for (int r = 0; r < 4; r++) c_[i][j][r] = 0.f;

#pragma unroll
        for (int q = 0; q < 12; q++) {
            uint32_t a_[4][4], b_[2][4];
#pragma unroll
            for (int mt = 0; mt < 4; mt++) {
                uint32_t row = 64 * wm + 16 * mt + (lane & 15);
                uint32_t kh  = q * 16 + 8 * (lane >> 4);
                ldsm4(a_[mt][0], a_[mt][1], a_[mt][2], a_[mt][3],
                      ab + (row * 200 + kh) * 2);
            }
#pragma unroll
            for (int p = 0; p < 2; p++) {
                uint32_t bn = 32 * wn + 16 * p + (lane & 7) + 8 * (lane >> 4);
                uint32_t kh = q * 16 + 8 * ((lane >> 3) & 1);
                ldsm4(b_[p][0], b_[p][1], b_[p][2], b_[p][3],
                      bb + (bn * 200 + kh) * 2);
            }
#pragma unroll
            for (int mt = 0; mt < 4; mt++) {
                mma_f16(c_[mt][0], a_[mt][0], a_[mt][1], a_[mt][2], a_[mt][3], b_[0][0], b_[0][1]);
                mma_f16(c_[mt][1], a_[mt][0], a_[mt][1], a_[mt][2], a_[mt][3], b_[0][2], b_[0][3]);
                mma_f16(c_[mt][2], a_[mt][0], a_[mt][1], a_[mt][2], a_[mt][3], b_[1][0], b_[1][1]);
                mma_f16(c_[mt][3], a_[mt][0], a_[mt][1], a_[mt][2], a_[mt][3], b_[1][2], b_[1][3]);
            }
        }
        __syncthreads();     // all warps done reading s_b

        if (nt < 7) {        // prefetch next B tile; overlaps epilogue
            for (int i = t; i < 3072; i += 256) {
                int r = i / 24, c = i % 24;
                cp16(bb + (uint32_t)(r * 200 + c * 8) * 2,
                     d_w5h + (size_t)((nt + 1) * 128 + r) * 192 + c * 8);
            }
            CP_COMMIT();
        }

        // epilogue: col-max over warp's 64 rows, relu, atomicMax into d_g
        float cm[8];
#pragma unroll
        for (int nq = 0; nq < 4; nq++) {
            float v0 = fmaxf(fmaxf(c_[0][nq][0], c_[0][nq][2]),
                             fmaxf(c_[1][nq][0], c_[1][nq][2]));
            v0 = fmaxf(v0, fmaxf(fmaxf(c_[2][nq][0], c_[2][nq][2]),
                                 fmaxf(c_[3][nq][0], c_[3][nq][2])));
            float v1 = fmaxf(fmaxf(c_[0][nq][1], c_[0][nq][3]),
                             fmaxf(c_[1][nq][1], c_[1][nq][3]));
            v1 = fmaxf(v1, fmaxf(fmaxf(c_[2][nq][1], c_[2][nq][3]),
                                 fmaxf(c_[3][nq][1], c_[3][nq][3])));
            cm[nq * 2 + 0] = v0;
            cm[nq * 2 + 1] = v1;
        }
#pragma unroll
        for (int off = 4; off < 32; off <<= 1)
#pragma unroll
            for (int j = 0; j < 8; j++)
                cm[j] = fmaxf(cm[j], __shfl_xor_sync(0xffffffffu, cm[j], off));
        if (lane < 4) {
            int colbase = nt * 128 + wn * 32 + 2 * lane;
#pragma unroll
            for (int nq = 0; nq < 4; nq++) {
                atomicMax((int*)&d_g[colbase + nq * 8],
                          __float_as_int(fmaxf(cm[2 * nq], 0.0f)));
                atomicMax((int*)&d_g[colbase + nq * 8 + 1],
                          __float_as_int(fmaxf(cm[2 * nq + 1], 0.0f)));
            }
        }
        if (nt < 7) CP_WAIT0();
        __syncthreads();     // s_b refilled, safe for next iteration
    }
}

// ---------------- head: 3 small GEMVs ----------------
__device__ __forceinline__ float blk_dot_reduce(float a) {
#pragma unroll
    for (int o = 16; o; o >>= 1) a += __shfl_xor_sync(0xffffffffu, a, o);
    __shared__ float s[4];
    int t = threadIdx.x;
    if ((t & 31) == 0) s[t >> 5] = a;
    __syncthreads();
    return s[0] + s[1] + s[2] + s[3];
}

__global__ void __launch_bounds__(128) k_head1(const float* __restrict__ wf1) {
    int t = threadIdx.x;
    const float4* wr = (const float4*)&wf1[(size_t)blockIdx.x * 1024];
    const float4* gr = (const float4*)d_g;
    float a = 0.f;
    for (int k = t; k < 256; k += 128) {
        float4 wv = __ldg(&wr[k]); float4 gv = gr[k];
        a += wv.x * gv.x + wv.y * gv.y + wv.z * gv.z + wv.w * gv.w;
    }
    float r = blk_dot_reduce(a);
    if (t == 0) d_f1[blockIdx.x] = fmaxf(r, 0.0f);
}

__global__ void __launch_bounds__(128) k_head2(const float* __restrict__ wf2) {
    int t = threadIdx.x;
    const float4* wr = (const float4*)&wf2[(size_t)blockIdx.x * 512];
    const float4* gr = (const float4*)d_f1;
    float a = 0.f;
    if (t < 128) {
        float4 wv = __ldg(&wr[t]); float4 gv = gr[t];
        a = wv.x * gv.x + wv.y * gv.y + wv.z * gv.z + wv.w * gv.w;
    }
    float r = blk_dot_reduce(a);
    if (t == 0) d_f2[blockIdx.x] = fmaxf(r, 0.0f);
}

__global__ void __launch_bounds__(128) k_head3(const float* __restrict__ wf3,
                                               float* __restrict__ out) {
    int t = threadIdx.x;
    const float4* wr = (const float4*)&wf3[(size_t)blockIdx.x * 256];
    const float4* gr = (const float4*)d_f2;
    float a = 0.f;
    if (t < 64) {
        float4 wv = __ldg(&wr[t]); float4 gv = gr[t];
        a = wv.x * gv.x + wv.y * gv.y + wv.z * gv.z + wv.w * gv.w;
    }
    float r = blk_dot_reduce(a);
    if (t == 0) out[blockIdx.x] = r;
}

// ---------------- launch ----------------
extern "C" void kernel_launch(void* const* d_in, const int* in_sizes, int n_in,
                              void* d_out, int out_size) {
    const float* x       = (const float*)d_in[0];
    const int*   indices = (const int*)d_in[2];   // indptr (d_in[1]) fixed K=16
    const float* w1  = (const float*)d_in[3];
    const float* w2  = (const float*)d_in[4];
    const float* w3  = (const float*)d_in[5];
    const float* w4  = (const float*)d_in[6];
    const float* w5  = (const float*)d_in[7];
    const float* wf1 = (const float*)d_in[8];
    const float* wf2 = (const float*)d_in[9];
    const float* wf3 = (const float*)d_in[10];
    float* out = (float*)d_out;

    const int SMEM_F = 35840 * 2 + 576 * 4;           // 74,176 B
    const int SMEM_5 = 2 * 128 * 200 * 2;             // 102,400 B -> 2 CTAs/SM
    cudaFuncSetAttribute(k_mlp1234, cudaFuncAttributeMaxDynamicSharedMemorySize, SMEM_F);
    cudaFuncSetAttribute(k_mlp5max, cudaFuncAttributeMaxDynamicSharedMemorySize, SMEM_5);

    k_prep   <<<836, 256>>>(w2, w3, w4, w5);
    k_mlp1234<<<NPTS / 128, 256, SMEM_F>>>(x, w1);
    k_gmax   <<<NPTS / 8,   256>>>(indices);
    k_mlp5max<<<NPTS / 128, 256, SMEM_5>>>();
    k_head1  <<<512, 128>>>(wf1);
    k_head2  <<<256, 128>>>(wf2);
    k_head3  <<<40,  128>>>(wf3, out);
}